// round 3
// baseline (speedup 1.0000x reference)
#include <cuda_runtime.h>

// Problem constants (GraphAttentionLayer: B=4, N=16384, E=262144, F=64)
#define FD   64
#define MAXB 4
#define MAXN 16384
#define MAXE 262144

#define LRELU_ALPHA 0.01f
#define EXP_CLAMP   1000000.0f
#define DENOM_EPS   1e-10f

// ---------------- device scratch (no allocations allowed) ----------------
__device__ float g_Wh[(size_t)MAXB * MAXN * FD];        // 16 MB
__device__ float g_sc[MAXB * MAXN];                     // Wh . a[0:64]
__device__ float g_sn[MAXB * MAXN];                     // Wh . a[64:128]
__device__ float g_denom[MAXB * MAXN];                  // seg-sum, then reciprocal
__device__ float g_xexp[(size_t)MAXB * MAXE];           // clipped exp (active edges only)

// ---------------- init: zero output accumulator + denom ----------------
__global__ __launch_bounds__(256)
void init_kernel(float* __restrict__ out, int nOut4, int nDenom) {
    int i = blockIdx.x * blockDim.x + threadIdx.x;
    int stride = gridDim.x * blockDim.x;
    float4 z = make_float4(0.f, 0.f, 0.f, 0.f);
    for (int k = i; k < nOut4; k += stride)
        reinterpret_cast<float4*>(out)[k] = z;
    for (int k = i; k < nDenom; k += stride)
        g_denom[k] = 0.f;
}

// ---------------- GEMM: Wh = h @ W^T, plus sc/sn epilogue ----------------
__global__ __launch_bounds__(256)
void gemm_kernel(const float* __restrict__ h, const float* __restrict__ W,
                 const float* __restrict__ a, int R) {
    __shared__ float sWt[64][68];   // W transposed: sWt[f][o]
    __shared__ float sh[64][65];    // h tile
    __shared__ float sa[2 * FD];

    int tid = threadIdx.x;
    int row0 = blockIdx.x * 64;

    for (int i = tid; i < 64 * 64; i += 256) {
        int o = i >> 6, f = i & 63;
        sWt[f][o] = W[i];
    }
    if (tid < 2 * FD) sa[tid] = a[tid];
    for (int i = tid; i < 64 * 64; i += 256) {
        int r = i >> 6, f = i & 63;
        sh[r][f] = h[(size_t)(row0 + r) * FD + f];
    }
    __syncthreads();

    int r  = tid >> 2;
    int og = (tid & 3) * 16;

    float acc[16];
#pragma unroll
    for (int j = 0; j < 16; j++) acc[j] = 0.f;

#pragma unroll
    for (int f = 0; f < 64; f++) {
        float hv = sh[r][f];
        const float4* wrow = reinterpret_cast<const float4*>(&sWt[f][og]);
#pragma unroll
        for (int j4 = 0; j4 < 4; j4++) {
            float4 w = wrow[j4];
            acc[j4 * 4 + 0] += hv * w.x;
            acc[j4 * 4 + 1] += hv * w.y;
            acc[j4 * 4 + 2] += hv * w.z;
            acc[j4 * 4 + 3] += hv * w.w;
        }
    }

    float scp = 0.f, snp = 0.f;
#pragma unroll
    for (int j = 0; j < 16; j++) {
        scp += acc[j] * sa[og + j];
        snp += acc[j] * sa[FD + og + j];
    }
    scp += __shfl_xor_sync(0xffffffffu, scp, 1);
    scp += __shfl_xor_sync(0xffffffffu, scp, 2);
    snp += __shfl_xor_sync(0xffffffffu, snp, 1);
    snp += __shfl_xor_sync(0xffffffffu, snp, 2);

    int row = row0 + r;
    float4* out4 = reinterpret_cast<float4*>(&g_Wh[(size_t)row * FD + og]);
#pragma unroll
    for (int j4 = 0; j4 < 4; j4++)
        out4[j4] = make_float4(acc[j4*4+0], acc[j4*4+1], acc[j4*4+2], acc[j4*4+3]);

    if ((tid & 3) == 0) {
        g_sc[row] = scp;
        g_sn[row] = snp;
    }
}

// ---------------- edge pass 1: x_exp + denominator segment sum ----------------
__global__ __launch_bounds__(256)
void edge1_kernel(const int2* __restrict__ edge, const float* __restrict__ ew,
                  const int* __restrict__ edge_num, int N, int E) {
    int b  = blockIdx.y;
    int en = edge_num[b];
    int e0 = blockIdx.x * blockDim.x;
    if (e0 >= en) return;                 // whole block in masked tail
    int e = e0 + threadIdx.x;
    if (e >= en || e >= E) return;
    size_t idx = (size_t)b * E + e;

    int2 ed = edge[idx];
    float s = g_sc[b * N + ed.x] + g_sn[b * N + ed.y];
    float t = ew[idx] * s;
    float att1 = (t >= 0.f) ? t : LRELU_ALPHA * t;          // leaky_relu
    float x = fminf(__expf(att1), EXP_CLAMP);               // clip(exp, 0, 1e6)
    g_xexp[idx] = x;
    atomicAdd(&g_denom[b * N + ed.x], x);                   // RED.E.ADD.F32
}

// ---------------- reciprocal pass: denom -> 1/(eps+denom) ----------------
__global__ __launch_bounds__(256)
void invd_kernel(int n) {
    int i = blockIdx.x * blockDim.x + threadIdx.x;
    if (i < n) g_denom[i] = 1.0f / (DENOM_EPS + g_denom[i]);
}

// ---------------- edge pass 2: scatter att * Wh[nbr] into output ----------------
// 16 lanes per edge; broadcast loads (no shuffles); att = xexp * inv_denom.
__global__ __launch_bounds__(256)
void edge2_kernel(const int2* __restrict__ edge, const int* __restrict__ edge_num,
                  float* __restrict__ hp, int N, int E) {
    int b  = blockIdx.y;
    int en = edge_num[b];
    if (blockIdx.x * 16 >= en) return;    // whole block in masked tail
    int e   = blockIdx.x * 16 + (threadIdx.x >> 4);
    int sub = threadIdx.x & 15;
    if (e >= en) return;
    size_t idx = (size_t)b * E + e;

    int2 ed = edge[idx];                          // broadcast within 16-lane group
    float att = g_xexp[idx] * g_denom[b * N + ed.x];

    const float4 w = reinterpret_cast<const float4*>(g_Wh)[((size_t)b * N + ed.y) * 16 + sub];
    float vx = w.x * att, vy = w.y * att, vz = w.z * att, vw = w.w * att;
    float* dst = hp + ((size_t)b * N + ed.x) * FD + sub * 4;
    asm volatile("red.global.add.v4.f32 [%0], {%1, %2, %3, %4};"
                 :: "l"(dst), "f"(vx), "f"(vy), "f"(vz), "f"(vw) : "memory");
}

// ---------------- final: in-place ReLU ----------------
__global__ __launch_bounds__(256)
void relu_kernel(float* __restrict__ out, int n4) {
    int i = blockIdx.x * blockDim.x + threadIdx.x;
    if (i >= n4) return;
    float4 v = reinterpret_cast<float4*>(out)[i];
    v.x = fmaxf(v.x, 0.f);
    v.y = fmaxf(v.y, 0.f);
    v.z = fmaxf(v.z, 0.f);
    v.w = fmaxf(v.w, 0.f);
    reinterpret_cast<float4*>(out)[i] = v;
}

// ---------------- launch ----------------
extern "C" void kernel_launch(void* const* d_in, const int* in_sizes, int n_in,
                              void* d_out, int out_size) {
    const float* h   = (const float*)d_in[0];
    const int2*  edg = (const int2*) d_in[1];
    const int*   en  = (const int*)  d_in[2];
    const float* ew  = (const float*)d_in[3];
    const float* W   = (const float*)d_in[4];
    const float* a   = (const float*)d_in[5];
    float* out = (float*)d_out;

    int B = in_sizes[2];                 // edge_num has B elements
    int E = in_sizes[3] / B;             // edge_weight is B*E
    int N = in_sizes[0] / (B * FD);      // h is B*N*F
    int R = B * N;

    init_kernel<<<256, 256>>>(out, out_size / 4, R);
    gemm_kernel<<<R / 64, 256>>>(h, W, a, R);

    dim3 g1((E + 255) / 256, B);
    edge1_kernel<<<g1, 256>>>(edg, ew, en, N, E);

    invd_kernel<<<(R + 255) / 256, 256>>>(R);

    dim3 g2((E + 15) / 16, B);
    edge2_kernel<<<g2, 256>>>(edg, en, out, N, E);

    relu_kernel<<<(out_size / 4 + 255) / 256, 256>>>(out, out_size / 4);
}

// round 5
// speedup vs baseline: 2.7127x; 2.7127x over previous
#include <cuda_runtime.h>

// Problem constants (GraphAttentionLayer: B=4, N=16384, E=262144, F=64)
#define FD   64
#define MAXB 4
#define MAXN 16384
#define MAXE 262144
#define MAXR (MAXB * MAXN)

#define LRELU_ALPHA 0.01f
#define EXP_CLAMP   1000000.0f
#define DENOM_EPS   1e-10f

// ---------------- device scratch (no allocations allowed) ----------------
__device__ float g_Wh[(size_t)MAXR * FD];          // 16 MB
__device__ float g_sc[MAXR];                       // Wh . a[0:64]
__device__ float g_sn[MAXR];                       // Wh . a[64:128]
__device__ float g_denom[MAXR];                    // segment sums of x_exp
__device__ float g_xexp[(size_t)MAXB * MAXE];      // clipped exp (active edges)
__device__ int   g_deg[MAXR];                      // per-node edge count
__device__ int   g_nodeoff[MAXR];                  // block-local exclusive scan
__device__ int   g_rowstart[MAXR];                 // CSR row starts
__device__ int   g_cursor[MAXR];                   // fill cursors
__device__ int   g_bsum[1024];                     // per-block scan sums
__device__ int   g_boff[1024];                     // scanned block offsets
__device__ int2  g_csr[(size_t)MAXB * MAXE];       // (nbr_global, bits(x_exp))

// ---------------- init: zero deg + denom (out is fully overwritten later) ----
__global__ __launch_bounds__(256)
void init_kernel(int R) {
    int i = blockIdx.x * blockDim.x + threadIdx.x;
    int stride = gridDim.x * blockDim.x;
    for (int k = i; k < R; k += stride) {
        g_denom[k] = 0.f;
        g_deg[k] = 0;
    }
}

// ---------------- GEMM: Wh = h @ W^T, 4x4 register tiling, sc/sn epilogue ----
// block: 64 rows x 64 cols; 256 threads as 16 row-groups x 16 col-groups.
__global__ __launch_bounds__(256)
void gemm_kernel(const float* __restrict__ h, const float* __restrict__ W,
                 const float* __restrict__ a, int R) {
    __shared__ float sWt[64][68];    // W transposed: sWt[f][o]
    __shared__ float sh_t[64 * 69];  // h transposed: sh_t[f*69 + r]; reused as sred
    __shared__ float sa[2 * FD];

    int tid = threadIdx.x;
    int row0 = blockIdx.x * 64;

    // load W (row-major [o][f]) into sWt[f][o]
    for (int i = tid; i < 64 * 64; i += 256) {
        int o = i >> 6, f = i & 63;
        sWt[f][o] = W[i];
    }
    if (tid < 2 * FD) sa[tid] = a[tid];
    // load h tile transposed: sh_t[f][r]
    for (int i = tid; i < 64 * 64; i += 256) {
        int r = i >> 6, f = i & 63;
        int row = row0 + r;
        sh_t[f * 69 + r] = (row < R) ? h[(size_t)row * FD + f] : 0.f;
    }
    __syncthreads();

    int rg = tid >> 4;      // row group 0..15 -> rows rg*4..rg*4+3
    int cg = tid & 15;      // col group 0..15 -> cols cg*4..cg*4+3

    float acc[4][4];
#pragma unroll
    for (int j = 0; j < 4; j++)
#pragma unroll
        for (int c = 0; c < 4; c++) acc[j][c] = 0.f;

#pragma unroll
    for (int f = 0; f < 64; f++) {
        float hv0 = sh_t[f * 69 + rg * 4 + 0];
        float hv1 = sh_t[f * 69 + rg * 4 + 1];
        float hv2 = sh_t[f * 69 + rg * 4 + 2];
        float hv3 = sh_t[f * 69 + rg * 4 + 3];
        float4 w = *reinterpret_cast<const float4*>(&sWt[f][cg * 4]);
        acc[0][0] += hv0 * w.x; acc[0][1] += hv0 * w.y; acc[0][2] += hv0 * w.z; acc[0][3] += hv0 * w.w;
        acc[1][0] += hv1 * w.x; acc[1][1] += hv1 * w.y; acc[1][2] += hv1 * w.z; acc[1][3] += hv1 * w.w;
        acc[2][0] += hv2 * w.x; acc[2][1] += hv2 * w.y; acc[2][2] += hv2 * w.z; acc[2][3] += hv2 * w.w;
        acc[3][0] += hv3 * w.x; acc[3][1] += hv3 * w.y; acc[3][2] += hv3 * w.z; acc[3][3] += hv3 * w.w;
    }

    // store Wh (coalesced: 16 cg lanes cover one row's 64 floats)
#pragma unroll
    for (int j = 0; j < 4; j++) {
        int row = row0 + rg * 4 + j;
        if (row < R)
            *reinterpret_cast<float4*>(&g_Wh[(size_t)row * FD + cg * 4]) =
                make_float4(acc[j][0], acc[j][1], acc[j][2], acc[j][3]);
    }

    // epilogue: per-thread partial dots with attention vector halves
    float4 av1 = *reinterpret_cast<const float4*>(&sa[cg * 4]);
    float4 av2 = *reinterpret_cast<const float4*>(&sa[FD + cg * 4]);
    float sp[4], sq[4];
#pragma unroll
    for (int j = 0; j < 4; j++) {
        sp[j] = acc[j][0] * av1.x + acc[j][1] * av1.y + acc[j][2] * av1.z + acc[j][3] * av1.w;
        sq[j] = acc[j][0] * av2.x + acc[j][1] * av2.y + acc[j][2] * av2.z + acc[j][3] * av2.w;
    }
    __syncthreads();                 // everyone done reading sh_t; reuse as sred
    float* sred = sh_t;              // sc at [row*17+cg], sn at [1088 + row*17+cg]
#pragma unroll
    for (int j = 0; j < 4; j++) {
        int row = rg * 4 + j;
        sred[row * 17 + cg] = sp[j];
        sred[1088 + row * 17 + cg] = sq[j];
    }
    __syncthreads();
    if (tid < 128) {
        int row = tid & 63;
        int base = (tid >= 64) ? 1088 : 0;
        float s = 0.f;
#pragma unroll
        for (int k = 0; k < 16; k++) s += sred[base + row * 17 + k];
        int grow = row0 + row;
        if (grow < R) {
            if (tid < 64) g_sc[grow] = s;
            else          g_sn[grow] = s;
        }
    }
}

// ---------------- edge pass 1: x_exp, denom segment sum, degree histogram ----
__global__ __launch_bounds__(256)
void edge1_kernel(const int2* __restrict__ edge, const float* __restrict__ ew,
                  const int* __restrict__ edge_num, int N, int E) {
    int b  = blockIdx.y;
    int en = edge_num[b];
    int e0 = blockIdx.x * blockDim.x;
    if (e0 >= en) return;
    int e = e0 + threadIdx.x;
    if (e >= en) return;
    size_t idx = (size_t)b * E + e;

    int2 ed = edge[idx];
    int node = b * N + ed.x;
    float s = g_sc[node] + g_sn[b * N + ed.y];
    float t = ew[idx] * s;
    float att1 = (t >= 0.f) ? t : LRELU_ALPHA * t;      // leaky_relu
    float x = fminf(__expf(att1), EXP_CLAMP);           // clip(exp, 0, 1e6)
    g_xexp[idx] = x;
    atomicAdd(&g_denom[node], x);
    atomicAdd(&g_deg[node], 1);
}

// ---------------- scan A: per-256-block exclusive scan of deg ----------------
__global__ __launch_bounds__(256)
void scanA_kernel(int R) {
    __shared__ int wsum[8];
    int i = blockIdx.x * 256 + threadIdx.x;
    int lane = threadIdx.x & 31, wid = threadIdx.x >> 5;
    int v = (i < R) ? g_deg[i] : 0;
    int s = v;
#pragma unroll
    for (int d = 1; d < 32; d <<= 1) {
        int t = __shfl_up_sync(0xffffffffu, s, d);
        if (lane >= d) s += t;
    }
    if (lane == 31) wsum[wid] = s;
    __syncthreads();
    if (wid == 0) {
        int ws = (lane < 8) ? wsum[lane] : 0;
#pragma unroll
        for (int d = 1; d < 8; d <<= 1) {
            int t = __shfl_up_sync(0xffffffffu, ws, d);
            if (lane >= d) ws += t;
        }
        if (lane < 8) wsum[lane] = ws;
    }
    __syncthreads();
    int excl = s - v + (wid ? wsum[wid - 1] : 0);
    if (i < R) g_nodeoff[i] = excl;
    if (threadIdx.x == 255) g_bsum[blockIdx.x] = excl + v;
}

// ---------------- scan B: scan the block sums (single block) ----------------
__global__ __launch_bounds__(256)
void scanB_kernel(int nb) {
    __shared__ int wsum[8];
    __shared__ int s_carry;
    if (threadIdx.x == 0) s_carry = 0;
    __syncthreads();
    int lane = threadIdx.x & 31, wid = threadIdx.x >> 5;
    for (int base = 0; base < nb; base += 256) {
        int i = base + threadIdx.x;
        int v = (i < nb) ? g_bsum[i] : 0;
        int s = v;
#pragma unroll
        for (int d = 1; d < 32; d <<= 1) {
            int t = __shfl_up_sync(0xffffffffu, s, d);
            if (lane >= d) s += t;
        }
        if (lane == 31) wsum[wid] = s;
        __syncthreads();
        if (wid == 0) {
            int ws = (lane < 8) ? wsum[lane] : 0;
#pragma unroll
            for (int d = 1; d < 8; d <<= 1) {
                int t = __shfl_up_sync(0xffffffffu, ws, d);
                if (lane >= d) ws += t;
            }
            if (lane < 8) wsum[lane] = ws;
        }
        __syncthreads();
        int carry = s_carry;
        int excl = carry + s - v + (wid ? wsum[wid - 1] : 0);
        if (i < nb) g_boff[i] = excl;
        __syncthreads();
        if (threadIdx.x == 255) s_carry = excl + v;
        __syncthreads();
    }
}

// ---------------- scan C: global row starts + cursor init ----------------
__global__ __launch_bounds__(256)
void scanC_kernel(int R) {
    int i = blockIdx.x * 256 + threadIdx.x;
    if (i >= R) return;
    int off = g_nodeoff[i] + g_boff[i >> 8];
    g_rowstart[i] = off;
    g_cursor[i] = off;
}

// ---------------- fill: scatter edges into CSR slots ----------------
__global__ __launch_bounds__(256)
void fill_kernel(const int2* __restrict__ edge, const int* __restrict__ edge_num,
                 int N, int E) {
    int b  = blockIdx.y;
    int en = edge_num[b];
    int e0 = blockIdx.x * blockDim.x;
    if (e0 >= en) return;
    int e = e0 + threadIdx.x;
    if (e >= en) return;
    size_t idx = (size_t)b * E + e;

    int2 ed = edge[idx];
    float x = g_xexp[idx];
    int p = atomicAdd(&g_cursor[b * N + ed.x], 1);
    g_csr[p] = make_int2(b * N + ed.y, __float_as_int(x));
}

// ---------------- node pass: gather-accumulate, normalize once, ReLU, store --
// 16 lanes per node; each lane owns a float4 of the 64-wide feature row.
__global__ __launch_bounds__(256)
void node_kernel(float* __restrict__ out, int R) {
    int g = blockIdx.x * 16 + (threadIdx.x >> 4);
    if (g >= R) return;
    int sub = threadIdx.x & 15;

    int start = g_rowstart[g];
    int deg   = g_deg[g];
    const float4* wh4 = reinterpret_cast<const float4*>(g_Wh);

    float4 acc = make_float4(0.f, 0.f, 0.f, 0.f);
    int2 c = (deg > 0) ? g_csr[start] : make_int2(0, 0);
    for (int i = 0; i < deg; i++) {
        int2 nc = (i + 1 < deg) ? g_csr[start + i + 1] : c;   // prefetch next
        float x = __int_as_float(c.y);
        float4 w = wh4[(size_t)c.x * 16 + sub];
        acc.x += x * w.x; acc.y += x * w.y; acc.z += x * w.z; acc.w += x * w.w;
        c = nc;
    }
    float inv = 1.0f / (DENOM_EPS + g_denom[g]);
    acc.x = fmaxf(acc.x * inv, 0.f);
    acc.y = fmaxf(acc.y * inv, 0.f);
    acc.z = fmaxf(acc.z * inv, 0.f);
    acc.w = fmaxf(acc.w * inv, 0.f);
    reinterpret_cast<float4*>(out)[(size_t)g * 16 + sub] = acc;
}

// ---------------- launch ----------------
extern "C" void kernel_launch(void* const* d_in, const int* in_sizes, int n_in,
                              void* d_out, int out_size) {
    const float* h   = (const float*)d_in[0];
    const int2*  edg = (const int2*) d_in[1];
    const int*   en  = (const int*)  d_in[2];
    const float* ew  = (const float*)d_in[3];
    const float* W   = (const float*)d_in[4];
    const float* a   = (const float*)d_in[5];
    float* out = (float*)d_out;

    int B = in_sizes[2];                 // edge_num has B elements
    int E = in_sizes[3] / B;             // edge_weight is B*E
    int N = in_sizes[0] / (B * FD);      // h is B*N*F
    int R = B * N;
    int nb = (R + 255) / 256;

    init_kernel<<<64, 256>>>(R);
    gemm_kernel<<<(R + 63) / 64, 256>>>(h, W, a, R);

    dim3 ge((E + 255) / 256, B);
    edge1_kernel<<<ge, 256>>>(edg, ew, en, N, E);

    scanA_kernel<<<nb, 256>>>(R);
    scanB_kernel<<<1, 256>>>(nb);
    scanC_kernel<<<nb, 256>>>(R);

    fill_kernel<<<ge, 256>>>(edg, en, N, E);

    node_kernel<<<(R + 15) / 16, 256>>>(out, R);
}

// round 6
// speedup vs baseline: 2.7875x; 1.0276x over previous
#include <cuda_runtime.h>

// Problem constants (GraphAttentionLayer: B=4, N=16384, E=262144, F=64)
#define FD   64
#define MAXB 4
#define MAXN 16384
#define MAXE 262144
#define MAXR (MAXB * MAXN)

#define LRELU_ALPHA 0.01f
#define EXP_CLAMP   1000000.0f
#define DENOM_EPS   1e-10f

// ---------------- device scratch (no allocations allowed) ----------------
__device__ float g_Wh[(size_t)MAXR * FD];          // 16 MB
__device__ float g_sc[MAXR];                       // Wh . a[0:64]
__device__ float g_sn[MAXR];                       // Wh . a[64:128]
__device__ float g_denom[MAXR];                    // segment sums of x_exp
__device__ int   g_deg[MAXR];                      // per-node edge count
__device__ int   g_nodeoff[MAXR];                  // block-local exclusive scan
__device__ int   g_cursor[MAXR];                   // fill cursors (end after fill)
__device__ int   g_bsum[1024];                     // per-block scan sums
__device__ int2  g_csr[(size_t)MAXB * MAXE];       // (nbr_global, bits(x_exp))

// ---------------- init: zero deg + denom ----------------
__global__ __launch_bounds__(256)
void init_kernel(int R) {
    int i = blockIdx.x * blockDim.x + threadIdx.x;
    int stride = gridDim.x * blockDim.x;
    for (int k = i; k < R; k += stride) {
        g_denom[k] = 0.f;
        g_deg[k] = 0;
    }
}

// ---------------- GEMM: Wh = h @ W^T, 4x4 register tiling, sc/sn epilogue ----
__global__ __launch_bounds__(256)
void gemm_kernel(const float* __restrict__ h, const float* __restrict__ W,
                 const float* __restrict__ a, int R) {
    __shared__ float sWt[64][68];    // W transposed: sWt[f][o]
    __shared__ float sh_t[64 * 69];  // h transposed: sh_t[f*69 + r]; reused as sred
    __shared__ float sa[2 * FD];

    int tid = threadIdx.x;
    int row0 = blockIdx.x * 64;

    for (int i = tid; i < 64 * 64; i += 256) {
        int o = i >> 6, f = i & 63;
        sWt[f][o] = W[i];
    }
    if (tid < 2 * FD) sa[tid] = a[tid];
    for (int i = tid; i < 64 * 64; i += 256) {
        int r = i >> 6, f = i & 63;
        int row = row0 + r;
        sh_t[f * 69 + r] = (row < R) ? h[(size_t)row * FD + f] : 0.f;
    }
    __syncthreads();

    int rg = tid >> 4;
    int cg = tid & 15;

    float acc[4][4];
#pragma unroll
    for (int j = 0; j < 4; j++)
#pragma unroll
        for (int c = 0; c < 4; c++) acc[j][c] = 0.f;

#pragma unroll
    for (int f = 0; f < 64; f++) {
        float hv0 = sh_t[f * 69 + rg * 4 + 0];
        float hv1 = sh_t[f * 69 + rg * 4 + 1];
        float hv2 = sh_t[f * 69 + rg * 4 + 2];
        float hv3 = sh_t[f * 69 + rg * 4 + 3];
        float4 w = *reinterpret_cast<const float4*>(&sWt[f][cg * 4]);
        acc[0][0] += hv0 * w.x; acc[0][1] += hv0 * w.y; acc[0][2] += hv0 * w.z; acc[0][3] += hv0 * w.w;
        acc[1][0] += hv1 * w.x; acc[1][1] += hv1 * w.y; acc[1][2] += hv1 * w.z; acc[1][3] += hv1 * w.w;
        acc[2][0] += hv2 * w.x; acc[2][1] += hv2 * w.y; acc[2][2] += hv2 * w.z; acc[2][3] += hv2 * w.w;
        acc[3][0] += hv3 * w.x; acc[3][1] += hv3 * w.y; acc[3][2] += hv3 * w.z; acc[3][3] += hv3 * w.w;
    }

#pragma unroll
    for (int j = 0; j < 4; j++) {
        int row = row0 + rg * 4 + j;
        if (row < R)
            *reinterpret_cast<float4*>(&g_Wh[(size_t)row * FD + cg * 4]) =
                make_float4(acc[j][0], acc[j][1], acc[j][2], acc[j][3]);
    }

    float4 av1 = *reinterpret_cast<const float4*>(&sa[cg * 4]);
    float4 av2 = *reinterpret_cast<const float4*>(&sa[FD + cg * 4]);
    float sp[4], sq[4];
#pragma unroll
    for (int j = 0; j < 4; j++) {
        sp[j] = acc[j][0] * av1.x + acc[j][1] * av1.y + acc[j][2] * av1.z + acc[j][3] * av1.w;
        sq[j] = acc[j][0] * av2.x + acc[j][1] * av2.y + acc[j][2] * av2.z + acc[j][3] * av2.w;
    }
    __syncthreads();
    float* sred = sh_t;
#pragma unroll
    for (int j = 0; j < 4; j++) {
        int row = rg * 4 + j;
        sred[row * 17 + cg] = sp[j];
        sred[1088 + row * 17 + cg] = sq[j];
    }
    __syncthreads();
    if (tid < 128) {
        int row = tid & 63;
        int base = (tid >= 64) ? 1088 : 0;
        float s = 0.f;
#pragma unroll
        for (int k = 0; k < 16; k++) s += sred[base + row * 17 + k];
        int grow = row0 + row;
        if (grow < R) {
            if (tid < 64) g_sc[grow] = s;
            else          g_sn[grow] = s;
        }
    }
}

// ---------------- count: degree histogram ----------------
__global__ __launch_bounds__(256)
void count_kernel(const int2* __restrict__ edge, const int* __restrict__ edge_num,
                  int N, int E) {
    int b  = blockIdx.y;
    int en = edge_num[b];
    int e0 = blockIdx.x * blockDim.x;
    if (e0 >= en) return;
    int e = e0 + threadIdx.x;
    if (e >= en) return;
    int2 ed = edge[(size_t)b * E + e];
    atomicAdd(&g_deg[b * N + ed.x], 1);
}

// ---------------- scan A: per-256-block exclusive scan of deg ----------------
__global__ __launch_bounds__(256)
void scanA_kernel(int R) {
    __shared__ int wsum[8];
    int i = blockIdx.x * 256 + threadIdx.x;
    int lane = threadIdx.x & 31, wid = threadIdx.x >> 5;
    int v = (i < R) ? g_deg[i] : 0;
    int s = v;
#pragma unroll
    for (int d = 1; d < 32; d <<= 1) {
        int t = __shfl_up_sync(0xffffffffu, s, d);
        if (lane >= d) s += t;
    }
    if (lane == 31) wsum[wid] = s;
    __syncthreads();
    if (wid == 0) {
        int ws = (lane < 8) ? wsum[lane] : 0;
#pragma unroll
        for (int d = 1; d < 8; d <<= 1) {
            int t = __shfl_up_sync(0xffffffffu, ws, d);
            if (lane >= d) ws += t;
        }
        if (lane < 8) wsum[lane] = ws;
    }
    __syncthreads();
    int excl = s - v + (wid ? wsum[wid - 1] : 0);
    if (i < R) g_nodeoff[i] = excl;
    if (threadIdx.x == 255) g_bsum[blockIdx.x] = excl + v;
}

// ---------------- scan C: each block self-computes its bsum prefix ------------
// Valid for nb <= 256 (R <= 65536). Writes fill cursors (= row starts).
__global__ __launch_bounds__(256)
void scanC_kernel(int R, int nb) {
    __shared__ int ssum[8];
    __shared__ int s_base;
    int bid = blockIdx.x;
    int tid = threadIdx.x;
    int lane = tid & 31, wid = tid >> 5;

    int v = (tid < bid && tid < nb) ? g_bsum[tid] : 0;
#pragma unroll
    for (int d = 16; d; d >>= 1) v += __shfl_xor_sync(0xffffffffu, v, d);
    if (lane == 0) ssum[wid] = v;
    __syncthreads();
    if (tid == 0) {
        int s = 0;
#pragma unroll
        for (int k = 0; k < 8; k++) s += ssum[k];
        s_base = s;
    }
    __syncthreads();

    int i = bid * 256 + tid;
    if (i < R) g_cursor[i] = g_nodeoff[i] + s_base;
}

// ---------------- edge+fill: compute x_exp, denom atomic, CSR scatter --------
__global__ __launch_bounds__(256)
void edgefill_kernel(const int2* __restrict__ edge, const float* __restrict__ ew,
                     const int* __restrict__ edge_num, int N, int E) {
    int b  = blockIdx.y;
    int en = edge_num[b];
    int e0 = blockIdx.x * blockDim.x;
    if (e0 >= en) return;
    int e = e0 + threadIdx.x;
    if (e >= en) return;
    size_t idx = (size_t)b * E + e;

    int2 ed = edge[idx];
    int node = b * N + ed.x;
    int nbrg = b * N + ed.y;
    float s = g_sc[node] + g_sn[nbrg];
    float t = ew[idx] * s;
    float att1 = (t >= 0.f) ? t : LRELU_ALPHA * t;      // leaky_relu
    float x = fminf(__expf(att1), EXP_CLAMP);           // clip(exp, 0, 1e6)
    atomicAdd(&g_denom[node], x);
    int p = atomicAdd(&g_cursor[node], 1);
    g_csr[p] = make_int2(nbrg, __float_as_int(x));
}

// ---------------- node pass: gather-accumulate, normalize, ReLU, store -------
// 16 lanes per node; 4-edge unroll for MLP. start = cursor_end - deg.
__global__ __launch_bounds__(256)
void node_kernel(float* __restrict__ out, int R) {
    int g = blockIdx.x * 16 + (threadIdx.x >> 4);
    if (g >= R) return;
    int sub = threadIdx.x & 15;

    int deg   = g_deg[g];
    int start = g_cursor[g] - deg;
    const float4* wh4 = reinterpret_cast<const float4*>(g_Wh);

    float4 acc = make_float4(0.f, 0.f, 0.f, 0.f);
    int i = 0;
    for (; i + 4 <= deg; i += 4) {
        int2 c0 = g_csr[start + i + 0];
        int2 c1 = g_csr[start + i + 1];
        int2 c2 = g_csr[start + i + 2];
        int2 c3 = g_csr[start + i + 3];
        float4 w0 = wh4[(size_t)c0.x * 16 + sub];
        float4 w1 = wh4[(size_t)c1.x * 16 + sub];
        float4 w2 = wh4[(size_t)c2.x * 16 + sub];
        float4 w3 = wh4[(size_t)c3.x * 16 + sub];
        float x0 = __int_as_float(c0.y), x1 = __int_as_float(c1.y);
        float x2 = __int_as_float(c2.y), x3 = __int_as_float(c3.y);
        acc.x += x0 * w0.x; acc.y += x0 * w0.y; acc.z += x0 * w0.z; acc.w += x0 * w0.w;
        acc.x += x1 * w1.x; acc.y += x1 * w1.y; acc.z += x1 * w1.z; acc.w += x1 * w1.w;
        acc.x += x2 * w2.x; acc.y += x2 * w2.y; acc.z += x2 * w2.z; acc.w += x2 * w2.w;
        acc.x += x3 * w3.x; acc.y += x3 * w3.y; acc.z += x3 * w3.z; acc.w += x3 * w3.w;
    }
    for (; i < deg; i++) {
        int2 c = g_csr[start + i];
        float x = __int_as_float(c.y);
        float4 w = wh4[(size_t)c.x * 16 + sub];
        acc.x += x * w.x; acc.y += x * w.y; acc.z += x * w.z; acc.w += x * w.w;
    }

    float inv = 1.0f / (DENOM_EPS + g_denom[g]);
    acc.x = fmaxf(acc.x * inv, 0.f);
    acc.y = fmaxf(acc.y * inv, 0.f);
    acc.z = fmaxf(acc.z * inv, 0.f);
    acc.w = fmaxf(acc.w * inv, 0.f);
    reinterpret_cast<float4*>(out)[(size_t)g * 16 + sub] = acc;
}

// ---------------- launch ----------------
extern "C" void kernel_launch(void* const* d_in, const int* in_sizes, int n_in,
                              void* d_out, int out_size) {
    const float* h   = (const float*)d_in[0];
    const int2*  edg = (const int2*) d_in[1];
    const int*   en  = (const int*)  d_in[2];
    const float* ew  = (const float*)d_in[3];
    const float* W   = (const float*)d_in[4];
    const float* a   = (const float*)d_in[5];
    float* out = (float*)d_out;

    int B = in_sizes[2];                 // edge_num has B elements
    int E = in_sizes[3] / B;             // edge_weight is B*E
    int N = in_sizes[0] / (B * FD);      // h is B*N*F
    int R = B * N;
    int nb = (R + 255) / 256;            // == 256 for this problem (scanC assumes <= 256)

    init_kernel<<<64, 256>>>(R);
    gemm_kernel<<<(R + 63) / 64, 256>>>(h, W, a, R);

    dim3 ge((E + 255) / 256, B);
    count_kernel<<<ge, 256>>>(edg, en, N, E);

    scanA_kernel<<<nb, 256>>>(R);
    scanC_kernel<<<nb, 256>>>(R, nb);

    edgefill_kernel<<<ge, 256>>>(edg, ew, en, N, E);

    node_kernel<<<(R + 15) / 16, 256>>>(out, R);
}

// round 7
// speedup vs baseline: 3.1242x; 1.1208x over previous
#include <cuda_runtime.h>

// Problem constants (GraphAttentionLayer: B=4, N=16384, E=262144, F=64)
#define FD   64
#define MAXB 4
#define MAXN 16384
#define MAXE 262144
#define MAXR (MAXB * MAXN)
#define CAP  128            // padded-CSR capacity per node (deg ~ Poisson(<=16))

#define LRELU_ALPHA 0.01f
#define EXP_CLAMP   1000000.0f
#define DENOM_EPS   1e-10f

// ---------------- device scratch (no allocations allowed) ----------------
__device__ float g_Wh[(size_t)MAXR * FD];          // 16 MB
__device__ float g_sc[MAXR];                       // Wh . a[0:64]
__device__ float g_sn[MAXR];                       // Wh . a[64:128]
__device__ float g_denom[MAXR];                    // segment sums of x_exp
__device__ int   g_deg[MAXR];                      // per-node cursor/degree
__device__ int2  g_csr[(size_t)MAXR * CAP];        // padded: (nbr_global, bits(x_exp)), 64 MB

// ---------------- GEMM: zero deg/denom + Wh = h @ W^T + sc/sn epilogue ----
// block: 64 rows x 64 cols; 256 threads as 16 row-groups x 16 col-groups.
__global__ __launch_bounds__(256)
void gemm_kernel(const float* __restrict__ h, const float* __restrict__ W,
                 const float* __restrict__ a, int R) {
    __shared__ float sWt[64][68];    // W transposed: sWt[f][o]
    __shared__ float sh_t[64 * 69];  // h transposed: sh_t[f*69 + r]; reused as sred
    __shared__ float sa[2 * FD];

    int tid = threadIdx.x;
    int row0 = blockIdx.x * 64;

    // fused init: this block owns denom/deg rows [row0, row0+64)
    if (tid < 64) {
        int row = row0 + tid;
        if (row < R) {
            g_denom[row] = 0.f;
            g_deg[row] = 0;
        }
    }

    for (int i = tid; i < 64 * 64; i += 256) {
        int o = i >> 6, f = i & 63;
        sWt[f][o] = W[i];
    }
    if (tid < 2 * FD) sa[tid] = a[tid];
    for (int i = tid; i < 64 * 64; i += 256) {
        int r = i >> 6, f = i & 63;
        int row = row0 + r;
        sh_t[f * 69 + r] = (row < R) ? h[(size_t)row * FD + f] : 0.f;
    }
    __syncthreads();

    int rg = tid >> 4;
    int cg = tid & 15;

    float acc[4][4];
#pragma unroll
    for (int j = 0; j < 4; j++)
#pragma unroll
        for (int c = 0; c < 4; c++) acc[j][c] = 0.f;

#pragma unroll
    for (int f = 0; f < 64; f++) {
        float hv0 = sh_t[f * 69 + rg * 4 + 0];
        float hv1 = sh_t[f * 69 + rg * 4 + 1];
        float hv2 = sh_t[f * 69 + rg * 4 + 2];
        float hv3 = sh_t[f * 69 + rg * 4 + 3];
        float4 w = *reinterpret_cast<const float4*>(&sWt[f][cg * 4]);
        acc[0][0] += hv0 * w.x; acc[0][1] += hv0 * w.y; acc[0][2] += hv0 * w.z; acc[0][3] += hv0 * w.w;
        acc[1][0] += hv1 * w.x; acc[1][1] += hv1 * w.y; acc[1][2] += hv1 * w.z; acc[1][3] += hv1 * w.w;
        acc[2][0] += hv2 * w.x; acc[2][1] += hv2 * w.y; acc[2][2] += hv2 * w.z; acc[2][3] += hv2 * w.w;
        acc[3][0] += hv3 * w.x; acc[3][1] += hv3 * w.y; acc[3][2] += hv3 * w.z; acc[3][3] += hv3 * w.w;
    }

#pragma unroll
    for (int j = 0; j < 4; j++) {
        int row = row0 + rg * 4 + j;
        if (row < R)
            *reinterpret_cast<float4*>(&g_Wh[(size_t)row * FD + cg * 4]) =
                make_float4(acc[j][0], acc[j][1], acc[j][2], acc[j][3]);
    }

    float4 av1 = *reinterpret_cast<const float4*>(&sa[cg * 4]);
    float4 av2 = *reinterpret_cast<const float4*>(&sa[FD + cg * 4]);
    float sp[4], sq[4];
#pragma unroll
    for (int j = 0; j < 4; j++) {
        sp[j] = acc[j][0] * av1.x + acc[j][1] * av1.y + acc[j][2] * av1.z + acc[j][3] * av1.w;
        sq[j] = acc[j][0] * av2.x + acc[j][1] * av2.y + acc[j][2] * av2.z + acc[j][3] * av2.w;
    }
    __syncthreads();
    float* sred = sh_t;
#pragma unroll
    for (int j = 0; j < 4; j++) {
        int row = rg * 4 + j;
        sred[row * 17 + cg] = sp[j];
        sred[1088 + row * 17 + cg] = sq[j];
    }
    __syncthreads();
    if (tid < 128) {
        int row = tid & 63;
        int base = (tid >= 64) ? 1088 : 0;
        float s = 0.f;
#pragma unroll
        for (int k = 0; k < 16; k++) s += sred[base + row * 17 + k];
        int grow = row0 + row;
        if (grow < R) {
            if (tid < 64) g_sc[grow] = s;
            else          g_sn[grow] = s;
        }
    }
}

// ---------------- edge+fill: x_exp, denom atomic, padded-CSR scatter --------
__global__ __launch_bounds__(256)
void edgefill_kernel(const int2* __restrict__ edge, const float* __restrict__ ew,
                     const int* __restrict__ edge_num, int N, int E) {
    int b  = blockIdx.y;
    int en = edge_num[b];
    int e0 = blockIdx.x * blockDim.x;
    if (e0 >= en) return;
    int e = e0 + threadIdx.x;
    if (e >= en) return;
    size_t idx = (size_t)b * E + e;

    int2 ed = edge[idx];
    int node = b * N + ed.x;
    int nbrg = b * N + ed.y;
    float s = g_sc[node] + g_sn[nbrg];
    float t = ew[idx] * s;
    float att1 = (t >= 0.f) ? t : LRELU_ALPHA * t;      // leaky_relu
    float x = fminf(__expf(att1), EXP_CLAMP);           // clip(exp, 0, 1e6)
    atomicAdd(&g_denom[node], x);
    int p = atomicAdd(&g_deg[node], 1);                 // cursor == degree counter
    if (p < CAP)
        g_csr[(size_t)node * CAP + p] = make_int2(nbrg, __float_as_int(x));
}

// ---------------- node pass: gather-accumulate, normalize, ReLU, store -------
// 16 lanes per node; 4-edge unroll for MLP.
__global__ __launch_bounds__(256)
void node_kernel(float* __restrict__ out, int R) {
    int g = blockIdx.x * 16 + (threadIdx.x >> 4);
    if (g >= R) return;
    int sub = threadIdx.x & 15;

    int deg = g_deg[g];
    if (deg > CAP) deg = CAP;
    const int2* row = &g_csr[(size_t)g * CAP];
    const float4* wh4 = reinterpret_cast<const float4*>(g_Wh);

    float4 acc = make_float4(0.f, 0.f, 0.f, 0.f);
    int i = 0;
    for (; i + 4 <= deg; i += 4) {
        int2 c0 = row[i + 0];
        int2 c1 = row[i + 1];
        int2 c2 = row[i + 2];
        int2 c3 = row[i + 3];
        float4 w0 = wh4[(size_t)c0.x * 16 + sub];
        float4 w1 = wh4[(size_t)c1.x * 16 + sub];
        float4 w2 = wh4[(size_t)c2.x * 16 + sub];
        float4 w3 = wh4[(size_t)c3.x * 16 + sub];
        float x0 = __int_as_float(c0.y), x1 = __int_as_float(c1.y);
        float x2 = __int_as_float(c2.y), x3 = __int_as_float(c3.y);
        acc.x += x0 * w0.x; acc.y += x0 * w0.y; acc.z += x0 * w0.z; acc.w += x0 * w0.w;
        acc.x += x1 * w1.x; acc.y += x1 * w1.y; acc.z += x1 * w1.z; acc.w += x1 * w1.w;
        acc.x += x2 * w2.x; acc.y += x2 * w2.y; acc.z += x2 * w2.z; acc.w += x2 * w2.w;
        acc.x += x3 * w3.x; acc.y += x3 * w3.y; acc.z += x3 * w3.z; acc.w += x3 * w3.w;
    }
    for (; i < deg; i++) {
        int2 c = row[i];
        float x = __int_as_float(c.y);
        float4 w = wh4[(size_t)c.x * 16 + sub];
        acc.x += x * w.x; acc.y += x * w.y; acc.z += x * w.z; acc.w += x * w.w;
    }

    float inv = 1.0f / (DENOM_EPS + g_denom[g]);
    acc.x = fmaxf(acc.x * inv, 0.f);
    acc.y = fmaxf(acc.y * inv, 0.f);
    acc.z = fmaxf(acc.z * inv, 0.f);
    acc.w = fmaxf(acc.w * inv, 0.f);
    reinterpret_cast<float4*>(out)[(size_t)g * 16 + sub] = acc;
}

// ---------------- launch ----------------
extern "C" void kernel_launch(void* const* d_in, const int* in_sizes, int n_in,
                              void* d_out, int out_size) {
    const float* h   = (const float*)d_in[0];
    const int2*  edg = (const int2*) d_in[1];
    const int*   en  = (const int*)  d_in[2];
    const float* ew  = (const float*)d_in[3];
    const float* W   = (const float*)d_in[4];
    const float* a   = (const float*)d_in[5];
    float* out = (float*)d_out;

    int B = in_sizes[2];                 // edge_num has B elements
    int E = in_sizes[3] / B;             // edge_weight is B*E
    int N = in_sizes[0] / (B * FD);      // h is B*N*F
    int R = B * N;

    gemm_kernel<<<(R + 63) / 64, 256>>>(h, W, a, R);

    dim3 ge((E + 255) / 256, B);
    edgefill_kernel<<<ge, 256>>>(edg, ew, en, N, E);

    node_kernel<<<(R + 15) / 16, 256>>>(out, R);
}

// round 8
// speedup vs baseline: 3.2335x; 1.0350x over previous
#include <cuda_runtime.h>

// Problem constants (GraphAttentionLayer: B=4, N=16384, E=262144, F=64)
#define FD   64
#define MAXB 4
#define MAXN 16384
#define MAXE 262144
#define MAXR (MAXB * MAXN)
#define CAP  128            // padded-CSR capacity per node (deg ~ Poisson(<=16))

#define LRELU_ALPHA 0.01f
#define EXP_CLAMP   1000000.0f
#define DENOM_EPS   1e-10f

// ---------------- device scratch (no allocations allowed) ----------------
__device__ float g_Wh[(size_t)MAXR * FD];          // 16 MB
__device__ float g_sc[MAXR];                       // Wh . a[0:64]
__device__ float g_sn[MAXR];                       // Wh . a[64:128]
__device__ float g_denom[MAXR];                    // segment sums of x_exp
__device__ int   g_deg[MAXR];                      // per-node cursor/degree
__device__ int2  g_csr[(size_t)MAXR * CAP];        // padded: (nbr_global, bits(x_exp)), 64 MB

// ---------------- GEMM: zero deg/denom + Wh = h @ W^T + sc/sn epilogue ----
// block: 64 rows x 64 cols; 256 threads as 16 row-groups x 16 col-groups.
// Inner loop: 2x LDS.128 (hv broadcast + w) per 16 FFMA.
__global__ __launch_bounds__(256)
void gemm_kernel(const float* __restrict__ h, const float* __restrict__ W,
                 const float* __restrict__ a, int R) {
    __shared__ float sWt[64][68];    // W transposed: sWt[f][o]
    __shared__ float sh_t[64 * 72];  // h transposed: sh_t[f*72 + r]; 16B-aligned rows
    __shared__ float sa[2 * FD];

    int tid = threadIdx.x;
    int row0 = blockIdx.x * 64;

    // fused init: this block owns denom/deg rows [row0, row0+64)
    if (tid < 64) {
        int row = row0 + tid;
        if (row < R) {
            g_denom[row] = 0.f;
            g_deg[row] = 0;
        }
    }

    for (int i = tid; i < 64 * 64; i += 256) {
        int o = i >> 6, f = i & 63;
        sWt[f][o] = W[i];
    }
    if (tid < 2 * FD) sa[tid] = a[tid];
    for (int i = tid; i < 64 * 64; i += 256) {
        int r = i >> 6, f = i & 63;
        int row = row0 + r;
        sh_t[f * 72 + r] = (row < R) ? h[(size_t)row * FD + f] : 0.f;
    }
    __syncthreads();

    int rg = tid >> 4;
    int cg = tid & 15;

    float acc[4][4];
#pragma unroll
    for (int j = 0; j < 4; j++)
#pragma unroll
        for (int c = 0; c < 4; c++) acc[j][c] = 0.f;

#pragma unroll
    for (int f = 0; f < 64; f++) {
        // one LDS.128, broadcast (2 distinct addrs per warp): rows rg*4..rg*4+3 at feature f
        float4 hv = *reinterpret_cast<const float4*>(&sh_t[f * 72 + rg * 4]);
        // one LDS.128: cols cg*4..cg*4+3 at feature f
        float4 w = *reinterpret_cast<const float4*>(&sWt[f][cg * 4]);
        acc[0][0] += hv.x * w.x; acc[0][1] += hv.x * w.y; acc[0][2] += hv.x * w.z; acc[0][3] += hv.x * w.w;
        acc[1][0] += hv.y * w.x; acc[1][1] += hv.y * w.y; acc[1][2] += hv.y * w.z; acc[1][3] += hv.y * w.w;
        acc[2][0] += hv.z * w.x; acc[2][1] += hv.z * w.y; acc[2][2] += hv.z * w.z; acc[2][3] += hv.z * w.w;
        acc[3][0] += hv.w * w.x; acc[3][1] += hv.w * w.y; acc[3][2] += hv.w * w.z; acc[3][3] += hv.w * w.w;
    }

#pragma unroll
    for (int j = 0; j < 4; j++) {
        int row = row0 + rg * 4 + j;
        if (row < R)
            *reinterpret_cast<float4*>(&g_Wh[(size_t)row * FD + cg * 4]) =
                make_float4(acc[j][0], acc[j][1], acc[j][2], acc[j][3]);
    }

    float4 av1 = *reinterpret_cast<const float4*>(&sa[cg * 4]);
    float4 av2 = *reinterpret_cast<const float4*>(&sa[FD + cg * 4]);
    float sp[4], sq[4];
#pragma unroll
    for (int j = 0; j < 4; j++) {
        sp[j] = acc[j][0] * av1.x + acc[j][1] * av1.y + acc[j][2] * av1.z + acc[j][3] * av1.w;
        sq[j] = acc[j][0] * av2.x + acc[j][1] * av2.y + acc[j][2] * av2.z + acc[j][3] * av2.w;
    }
    __syncthreads();
    float* sred = sh_t;              // reuse (needs 2176 floats < 4608)
#pragma unroll
    for (int j = 0; j < 4; j++) {
        int row = rg * 4 + j;
        sred[row * 17 + cg] = sp[j];
        sred[1088 + row * 17 + cg] = sq[j];
    }
    __syncthreads();
    if (tid < 128) {
        int row = tid & 63;
        int base = (tid >= 64) ? 1088 : 0;
        float s = 0.f;
#pragma unroll
        for (int k = 0; k < 16; k++) s += sred[base + row * 17 + k];
        int grow = row0 + row;
        if (grow < R) {
            if (tid < 64) g_sc[grow] = s;
            else          g_sn[grow] = s;
        }
    }
}

// ---------------- edge+fill: x_exp, denom atomic, padded-CSR scatter --------
__global__ __launch_bounds__(256)
void edgefill_kernel(const int2* __restrict__ edge, const float* __restrict__ ew,
                     const int* __restrict__ edge_num, int N, int E) {
    int b  = blockIdx.y;
    int en = edge_num[b];
    int e0 = blockIdx.x * blockDim.x;
    if (e0 >= en) return;
    int e = e0 + threadIdx.x;
    if (e >= en) return;
    size_t idx = (size_t)b * E + e;

    int2 ed = edge[idx];
    int node = b * N + ed.x;
    int nbrg = b * N + ed.y;
    float s = g_sc[node] + g_sn[nbrg];
    float t = ew[idx] * s;
    float att1 = (t >= 0.f) ? t : LRELU_ALPHA * t;      // leaky_relu
    float x = fminf(__expf(att1), EXP_CLAMP);           // clip(exp, 0, 1e6)
    atomicAdd(&g_denom[node], x);
    int p = atomicAdd(&g_deg[node], 1);                 // cursor == degree counter
    if (p < CAP)
        g_csr[(size_t)node * CAP + p] = make_int2(nbrg, __float_as_int(x));
}

// ---------------- node pass: gather-accumulate, normalize, ReLU, store -------
// 16 lanes per node; 4-edge unroll for MLP.
__global__ __launch_bounds__(256)
void node_kernel(float* __restrict__ out, int R) {
    int g = blockIdx.x * 16 + (threadIdx.x >> 4);
    if (g >= R) return;
    int sub = threadIdx.x & 15;

    int deg = g_deg[g];
    if (deg > CAP) deg = CAP;
    const int2* row = &g_csr[(size_t)g * CAP];
    const float4* wh4 = reinterpret_cast<const float4*>(g_Wh);

    float4 acc = make_float4(0.f, 0.f, 0.f, 0.f);
    int i = 0;
    for (; i + 4 <= deg; i += 4) {
        int2 c0 = row[i + 0];
        int2 c1 = row[i + 1];
        int2 c2 = row[i + 2];
        int2 c3 = row[i + 3];
        float4 w0 = wh4[(size_t)c0.x * 16 + sub];
        float4 w1 = wh4[(size_t)c1.x * 16 + sub];
        float4 w2 = wh4[(size_t)c2.x * 16 + sub];
        float4 w3 = wh4[(size_t)c3.x * 16 + sub];
        float x0 = __int_as_float(c0.y), x1 = __int_as_float(c1.y);
        float x2 = __int_as_float(c2.y), x3 = __int_as_float(c3.y);
        acc.x += x0 * w0.x; acc.y += x0 * w0.y; acc.z += x0 * w0.z; acc.w += x0 * w0.w;
        acc.x += x1 * w1.x; acc.y += x1 * w1.y; acc.z += x1 * w1.z; acc.w += x1 * w1.w;
        acc.x += x2 * w2.x; acc.y += x2 * w2.y; acc.z += x2 * w2.z; acc.w += x2 * w2.w;
        acc.x += x3 * w3.x; acc.y += x3 * w3.y; acc.z += x3 * w3.z; acc.w += x3 * w3.w;
    }
    for (; i < deg; i++) {
        int2 c = row[i];
        float x = __int_as_float(c.y);
        float4 w = wh4[(size_t)c.x * 16 + sub];
        acc.x += x * w.x; acc.y += x * w.y; acc.z += x * w.z; acc.w += x * w.w;
    }

    float inv = 1.0f / (DENOM_EPS + g_denom[g]);
    acc.x = fmaxf(acc.x * inv, 0.f);
    acc.y = fmaxf(acc.y * inv, 0.f);
    acc.z = fmaxf(acc.z * inv, 0.f);
    acc.w = fmaxf(acc.w * inv, 0.f);
    reinterpret_cast<float4*>(out)[(size_t)g * 16 + sub] = acc;
}

// ---------------- launch ----------------
extern "C" void kernel_launch(void* const* d_in, const int* in_sizes, int n_in,
                              void* d_out, int out_size) {
    const float* h   = (const float*)d_in[0];
    const int2*  edg = (const int2*) d_in[1];
    const int*   en  = (const int*)  d_in[2];
    const float* ew  = (const float*)d_in[3];
    const float* W   = (const float*)d_in[4];
    const float* a   = (const float*)d_in[5];
    float* out = (float*)d_out;

    int B = in_sizes[2];                 // edge_num has B elements
    int E = in_sizes[3] / B;             // edge_weight is B*E
    int N = in_sizes[0] / (B * FD);      // h is B*N*F
    int R = B * N;

    gemm_kernel<<<(R + 63) / 64, 256>>>(h, W, a, R);

    dim3 ge((E + 255) / 256, B);
    edgefill_kernel<<<ge, 256>>>(edg, ew, en, N, E);

    node_kernel<<<(R + 15) / 16, 256>>>(out, R);
}

// round 9
// speedup vs baseline: 3.4694x; 1.0730x over previous
#include <cuda_runtime.h>
#include <cstdint>

// Problem constants (GraphAttentionLayer: B=4, N=16384, E=262144, F=64)
#define FD   64
#define MAXB 4
#define MAXN 16384
#define MAXE 262144
#define MAXR (MAXB * MAXN)
#define CAP  128            // padded-CSR capacity per node (deg ~ Poisson(<=16))

#define LRELU_ALPHA 0.01f
#define EXP_CLAMP   1000000.0f
#define DENOM_EPS   1e-10f

#define GEMM_GRID 296       // 2 per SM (148 SMs)

// ---------------- device scratch (no allocations allowed) ----------------
__device__ float g_Wh[(size_t)MAXR * FD];          // 16 MB
__device__ float g_sc[MAXR];                       // Wh . a[0:64]
__device__ float g_sn[MAXR];                       // Wh . a[64:128]
__device__ float g_denom[MAXR];                    // segment sums of x_exp
__device__ int   g_deg[MAXR];                      // per-node cursor/degree
__device__ int2  g_csr[(size_t)MAXR * CAP];        // padded: (nbr_global, bits(x_exp))

// ---------------- packed fp32x2 helpers (sm_103a FFMA2 path) ----------------
#define FFMA2(d, a, b, c) \
    asm("fma.rn.f32x2 %0, %1, %2, %3;" : "=l"(d) : "l"(a), "l"(b), "l"(c))
#define SPLAT2(d, x) \
    asm("mov.b64 %0, {%1, %2};" : "=l"(d) : "r"(x), "r"(x))
#define UNPACK2(lo, hi, v) \
    asm("mov.b64 {%0, %1}, %2;" : "=f"(lo), "=f"(hi) : "l"(v))

__device__ __forceinline__ uint32_t smem_u32(const void* p) {
    return (uint32_t)__cvta_generic_to_shared(p);
}

// dynamic smem layout (floats): sW[64*68] | sa[128] | sh[2][64*72]
#define SW_OFF    0
#define SA_OFF    (64 * 68)
#define SH_OFF    (64 * 68 + 128)
#define SH_STRIDE (64 * 72)
#define GEMM_SMEM_BYTES ((SH_OFF + 2 * SH_STRIDE) * 4)   // 54784 B

// ---------------- GEMM: persistent tiles, cp.async double-buffer, FFMA2 ----
// tile = 64 rows x 64 cols; 256 threads = 16 row-groups x 16 col-groups,
// each thread computes 4x4 outputs as 2 row-pairs x 4 cols in f32x2.
__global__ __launch_bounds__(256)
void gemm_kernel(const float* __restrict__ h, const float* __restrict__ W,
                 const float* __restrict__ a, int R, int NT) {
    extern __shared__ float smem[];
    float* sW = smem + SW_OFF;
    float* sa = smem + SA_OFF;
    int tid = threadIdx.x;

    // load W transposed (sW[f*68+o]) + attention vector -- once per block
    for (int i = tid; i < 64 * 64; i += 256) {
        int o = i >> 6, f = i & 63;
        sW[f * 68 + o] = W[i];
    }
    if (tid < 128) sa[tid] = a[tid];

    int rg = tid >> 4;      // row group: rows rg*4..rg*4+3
    int cg = tid & 15;      // col group: cols cg*4..cg*4+3

    int t0 = blockIdx.x;

    // prefetch first tile into buffer 0 (cp.async.4: gmem coalesced, smem transposed)
    {
        float* dst = smem + SH_OFF;
        if (t0 < NT) {
            int row0 = t0 * 64;
#pragma unroll
            for (int k = 0; k < 16; k++) {
                int i = tid + k * 256;
                int f = i & 63, r = i >> 6;
                int row = row0 + r;
                if (row < R)
                    asm volatile("cp.async.ca.shared.global [%0], [%1], 4;"
                                 :: "r"(smem_u32(dst + f * 72 + r)),
                                    "l"(h + (size_t)row * FD + f) : "memory");
            }
        }
        asm volatile("cp.async.commit_group;" ::: "memory");
    }

    int buf = 0;
    for (int t = t0; t < NT; t += GEMM_GRID) {
        int row0 = t * 64;
        int tn = t + GEMM_GRID;
        float* cur = smem + SH_OFF + buf * SH_STRIDE;
        float* nxt = smem + SH_OFF + (buf ^ 1) * SH_STRIDE;

        // fused init: zero denom/deg for this tile's rows
        if (tid < 64) {
            int row = row0 + tid;
            if (row < R) { g_denom[row] = 0.f; g_deg[row] = 0; }
        }

        // prefetch next tile while computing this one
        if (tn < NT) {
            int nrow0 = tn * 64;
#pragma unroll
            for (int k = 0; k < 16; k++) {
                int i = tid + k * 256;
                int f = i & 63, r = i >> 6;
                int row = nrow0 + r;
                if (row < R)
                    asm volatile("cp.async.ca.shared.global [%0], [%1], 4;"
                                 :: "r"(smem_u32(nxt + f * 72 + r)),
                                    "l"(h + (size_t)row * FD + f) : "memory");
            }
            asm volatile("cp.async.commit_group;" ::: "memory");
            asm volatile("cp.async.wait_group 1;" ::: "memory");   // cur tile done
        } else {
            asm volatile("cp.async.wait_group 0;" ::: "memory");
        }
        __syncthreads();

        // mainloop: 1 LDS.128 hv (row pairs) + 1 LDS.128 w + 4 splats + 8 FFMA2
        unsigned long long acc2[2][4];
#pragma unroll
        for (int p = 0; p < 2; p++)
#pragma unroll
            for (int c = 0; c < 4; c++) acc2[p][c] = 0ull;

#pragma unroll 16
        for (int f = 0; f < 64; f++) {
            ulonglong2 hvp = *reinterpret_cast<const ulonglong2*>(&cur[f * 72 + rg * 4]);
            float4 w = *reinterpret_cast<const float4*>(&sW[f * 68 + cg * 4]);
            unsigned long long w0, w1, w2, w3;
            SPLAT2(w0, __float_as_uint(w.x));
            SPLAT2(w1, __float_as_uint(w.y));
            SPLAT2(w2, __float_as_uint(w.z));
            SPLAT2(w3, __float_as_uint(w.w));
            FFMA2(acc2[0][0], hvp.x, w0, acc2[0][0]);
            FFMA2(acc2[0][1], hvp.x, w1, acc2[0][1]);
            FFMA2(acc2[0][2], hvp.x, w2, acc2[0][2]);
            FFMA2(acc2[0][3], hvp.x, w3, acc2[0][3]);
            FFMA2(acc2[1][0], hvp.y, w0, acc2[1][0]);
            FFMA2(acc2[1][1], hvp.y, w1, acc2[1][1]);
            FFMA2(acc2[1][2], hvp.y, w2, acc2[1][2]);
            FFMA2(acc2[1][3], hvp.y, w3, acc2[1][3]);
        }

        // unpack: accs[j][c], rows j = rg*4 + (2p + half)
        float accs[4][4];
#pragma unroll
        for (int p = 0; p < 2; p++)
#pragma unroll
            for (int c = 0; c < 4; c++)
                UNPACK2(accs[2 * p][c], accs[2 * p + 1][c], acc2[p][c]);

        // store Wh
#pragma unroll
        for (int j = 0; j < 4; j++) {
            int row = row0 + rg * 4 + j;
            if (row < R)
                *reinterpret_cast<float4*>(&g_Wh[(size_t)row * FD + cg * 4]) =
                    make_float4(accs[j][0], accs[j][1], accs[j][2], accs[j][3]);
        }

        // sc/sn epilogue: partial dots + 16-lane shuffle reduction over cg
        float4 av1 = *reinterpret_cast<const float4*>(&sa[cg * 4]);
        float4 av2 = *reinterpret_cast<const float4*>(&sa[64 + cg * 4]);
        float sp[4], sq[4];
#pragma unroll
        for (int j = 0; j < 4; j++) {
            sp[j] = accs[j][0] * av1.x + accs[j][1] * av1.y + accs[j][2] * av1.z + accs[j][3] * av1.w;
            sq[j] = accs[j][0] * av2.x + accs[j][1] * av2.y + accs[j][2] * av2.z + accs[j][3] * av2.w;
        }
#pragma unroll
        for (int m = 1; m < 16; m <<= 1) {
#pragma unroll
            for (int j = 0; j < 4; j++) {
                sp[j] += __shfl_xor_sync(0xffffffffu, sp[j], m);
                sq[j] += __shfl_xor_sync(0xffffffffu, sq[j], m);
            }
        }
        if (cg == 0) {
#pragma unroll
            for (int j = 0; j < 4; j++) {
                int row = row0 + rg * 4 + j;
                if (row < R) { g_sc[row] = sp[j]; g_sn[row] = sq[j]; }
            }
        }

        __syncthreads();   // all reads of cur done before next iter overwrites it
        buf ^= 1;
    }
}

// ---------------- edge+fill: x_exp, denom atomic, padded-CSR scatter --------
__global__ __launch_bounds__(256)
void edgefill_kernel(const int2* __restrict__ edge, const float* __restrict__ ew,
                     const int* __restrict__ edge_num, int N, int E) {
    int b  = blockIdx.y;
    int en = edge_num[b];
    int e0 = blockIdx.x * blockDim.x;
    if (e0 >= en) return;
    int e = e0 + threadIdx.x;
    if (e >= en) return;
    size_t idx = (size_t)b * E + e;

    int2 ed = edge[idx];
    int node = b * N + ed.x;
    int nbrg = b * N + ed.y;
    float s = g_sc[node] + g_sn[nbrg];
    float t = ew[idx] * s;
    float att1 = (t >= 0.f) ? t : LRELU_ALPHA * t;      // leaky_relu
    float x = fminf(__expf(att1), EXP_CLAMP);           // clip(exp, 0, 1e6)
    atomicAdd(&g_denom[node], x);
    int p = atomicAdd(&g_deg[node], 1);                 // cursor == degree counter
    if (p < CAP)
        g_csr[(size_t)node * CAP + p] = make_int2(nbrg, __float_as_int(x));
}

// ---------------- node pass: gather-accumulate, normalize, ReLU, store -------
__global__ __launch_bounds__(256)
void node_kernel(float* __restrict__ out, int R) {
    int g = blockIdx.x * 16 + (threadIdx.x >> 4);
    if (g >= R) return;
    int sub = threadIdx.x & 15;

    int deg = g_deg[g];
    if (deg > CAP) deg = CAP;
    const int2* row = &g_csr[(size_t)g * CAP];
    const float4* wh4 = reinterpret_cast<const float4*>(g_Wh);

    float4 acc = make_float4(0.f, 0.f, 0.f, 0.f);
    int i = 0;
    for (; i + 4 <= deg; i += 4) {
        int2 c0 = row[i + 0];
        int2 c1 = row[i + 1];
        int2 c2 = row[i + 2];
        int2 c3 = row[i + 3];
        float4 w0 = wh4[(size_t)c0.x * 16 + sub];
        float4 w1 = wh4[(size_t)c1.x * 16 + sub];
        float4 w2 = wh4[(size_t)c2.x * 16 + sub];
        float4 w3 = wh4[(size_t)c3.x * 16 + sub];
        float x0 = __int_as_float(c0.y), x1 = __int_as_float(c1.y);
        float x2 = __int_as_float(c2.y), x3 = __int_as_float(c3.y);
        acc.x += x0 * w0.x; acc.y += x0 * w0.y; acc.z += x0 * w0.z; acc.w += x0 * w0.w;
        acc.x += x1 * w1.x; acc.y += x1 * w1.y; acc.z += x1 * w1.z; acc.w += x1 * w1.w;
        acc.x += x2 * w2.x; acc.y += x2 * w2.y; acc.z += x2 * w2.z; acc.w += x2 * w2.w;
        acc.x += x3 * w3.x; acc.y += x3 * w3.y; acc.z += x3 * w3.z; acc.w += x3 * w3.w;
    }
    for (; i < deg; i++) {
        int2 c = row[i];
        float x = __int_as_float(c.y);
        float4 w = wh4[(size_t)c.x * 16 + sub];
        acc.x += x * w.x; acc.y += x * w.y; acc.z += x * w.z; acc.w += x * w.w;
    }

    float inv = 1.0f / (DENOM_EPS + g_denom[g]);
    acc.x = fmaxf(acc.x * inv, 0.f);
    acc.y = fmaxf(acc.y * inv, 0.f);
    acc.z = fmaxf(acc.z * inv, 0.f);
    acc.w = fmaxf(acc.w * inv, 0.f);
    reinterpret_cast<float4*>(out)[(size_t)g * 16 + sub] = acc;
}

// ---------------- launch ----------------
extern "C" void kernel_launch(void* const* d_in, const int* in_sizes, int n_in,
                              void* d_out, int out_size) {
    const float* h   = (const float*)d_in[0];
    const int2*  edg = (const int2*) d_in[1];
    const int*   en  = (const int*)  d_in[2];
    const float* ew  = (const float*)d_in[3];
    const float* W   = (const float*)d_in[4];
    const float* a   = (const float*)d_in[5];
    float* out = (float*)d_out;

    int B = in_sizes[2];                 // edge_num has B elements
    int E = in_sizes[3] / B;             // edge_weight is B*E
    int N = in_sizes[0] / (B * FD);      // h is B*N*F
    int R = B * N;
    int NT = (R + 63) / 64;

    // opt in to >48KB dynamic smem (idempotent; executes at capture time)
    cudaFuncSetAttribute(gemm_kernel,
                         cudaFuncAttributeMaxDynamicSharedMemorySize,
                         GEMM_SMEM_BYTES);

    gemm_kernel<<<GEMM_GRID, 256, GEMM_SMEM_BYTES>>>(h, W, a, R, NT);

    dim3 ge((E + 255) / 256, B);
    edgefill_kernel<<<ge, 256>>>(edg, ew, en, N, E);

    node_kernel<<<(R + 15) / 16, 256>>>(out, R);
}

// round 10
// speedup vs baseline: 3.5769x; 1.0310x over previous
#include <cuda_runtime.h>
#include <cstdint>

// Problem constants (GraphAttentionLayer: B=4, N=16384, E=262144, F=64)
#define FD   64
#define MAXB 4
#define MAXN 16384
#define MAXE 262144
#define MAXR (MAXB * MAXN)
#define CAP  128            // padded-CSR capacity per node (deg ~ Poisson(<=16))

#define LRELU_ALPHA 0.01f
#define EXP_CLAMP   1000000.0f
#define DENOM_EPS   1e-10f

#define GEMM_GRID 256       // NT=512 -> exactly 2 tiles/block, all co-resident
#define TROWS     128       // tile rows

// ---------------- device scratch (no allocations allowed) ----------------
__device__ float g_Wh[(size_t)MAXR * FD];          // 16 MB
__device__ float g_sc[MAXR];                       // Wh . a[0:64]
__device__ float g_sn[MAXR];                       // Wh . a[64:128]
__device__ float g_denom[MAXR];                    // segment sums of x_exp
__device__ int   g_deg[MAXR];                      // per-node cursor/degree
__device__ int2  g_csr[(size_t)MAXR * CAP];        // padded: (nbr_global, bits(x_exp))

// ---------------- packed fp32x2 helpers (sm_103a FFMA2 path) ----------------
#define FFMA2(d, a, b, c) \
    asm("fma.rn.f32x2 %0, %1, %2, %3;" : "=l"(d) : "l"(a), "l"(b), "l"(c))
#define SPLAT2(d, x) \
    asm("mov.b64 %0, {%1, %2};" : "=l"(d) : "r"(x), "r"(x))
#define UNPACK2(lo, hi, v) \
    asm("mov.b64 {%0, %1}, %2;" : "=f"(lo), "=f"(hi) : "l"(v))

__device__ __forceinline__ uint32_t smem_u32(const void* p) {
    return (uint32_t)__cvta_generic_to_shared(p);
}

// dynamic smem layout (floats): sW[64*68] | sa[128] | sh[2][64*132]
#define SW_OFF    0
#define SA_OFF    (64 * 68)
#define SH_OFF    (64 * 68 + 128)
#define SH_STRIDE (64 * 132)
#define GEMM_SMEM_BYTES ((SH_OFF + 2 * SH_STRIDE) * 4)   // 85,504 B -> 2 blocks/SM

// ---------------- GEMM: persistent 128x64 tiles, cp.async dbuf, FFMA2 -------
// 256 threads = 16 row-groups (8 rows each) x 16 col-groups (4 cols each).
__global__ __launch_bounds__(256)
void gemm_kernel(const float* __restrict__ h, const float* __restrict__ W,
                 const float* __restrict__ a, int R, int NT) {
    extern __shared__ float smem[];
    float* sW = smem + SW_OFF;
    float* sa = smem + SA_OFF;
    int tid = threadIdx.x;

    // load W transposed (sW[f*68+o]) + attention vector -- once per block
    for (int i = tid; i < 64 * 64; i += 256) {
        int o = i >> 6, f = i & 63;
        sW[f * 68 + o] = W[i];
    }
    if (tid < 128) sa[tid] = a[tid];

    int rg = tid >> 4;      // row group: rows rg*8 .. rg*8+7
    int cg = tid & 15;      // col group: cols cg*4 .. cg*4+3

    int t0 = blockIdx.x;

    // prefetch first tile into buffer 0 (cp.async 4B: gmem coalesced, smem transposed)
    {
        float* dst = smem + SH_OFF;
        if (t0 < NT) {
            int row0 = t0 * TROWS;
#pragma unroll
            for (int k = 0; k < 32; k++) {
                int i = tid + k * 256;
                int f = i & 63, r = i >> 6;
                int row = row0 + r;
                if (row < R)
                    asm volatile("cp.async.ca.shared.global [%0], [%1], 4;"
                                 :: "r"(smem_u32(dst + f * 132 + r)),
                                    "l"(h + (size_t)row * FD + f) : "memory");
            }
        }
        asm volatile("cp.async.commit_group;" ::: "memory");
    }

    int buf = 0;
    for (int t = t0; t < NT; t += GEMM_GRID) {
        int row0 = t * TROWS;
        int tn = t + GEMM_GRID;
        float* cur = smem + SH_OFF + buf * SH_STRIDE;
        float* nxt = smem + SH_OFF + (buf ^ 1) * SH_STRIDE;

        // fused init: zero denom/deg for this tile's rows
        if (tid < TROWS) {
            int row = row0 + tid;
            if (row < R) { g_denom[row] = 0.f; g_deg[row] = 0; }
        }

        // prefetch next tile while computing this one
        if (tn < NT) {
            int nrow0 = tn * TROWS;
#pragma unroll
            for (int k = 0; k < 32; k++) {
                int i = tid + k * 256;
                int f = i & 63, r = i >> 6;
                int row = nrow0 + r;
                if (row < R)
                    asm volatile("cp.async.ca.shared.global [%0], [%1], 4;"
                                 :: "r"(smem_u32(nxt + f * 132 + r)),
                                    "l"(h + (size_t)row * FD + f) : "memory");
            }
            asm volatile("cp.async.commit_group;" ::: "memory");
            asm volatile("cp.async.wait_group 1;" ::: "memory");   // cur tile ready
        } else {
            asm volatile("cp.async.wait_group 0;" ::: "memory");
        }
        __syncthreads();

        // mainloop: 3 LDS.128 + 4 splats + 16 FFMA2 per f
        unsigned long long acc2[4][4];   // [row-pair p][col c]
#pragma unroll
        for (int p = 0; p < 4; p++)
#pragma unroll
            for (int c = 0; c < 4; c++) acc2[p][c] = 0ull;

#pragma unroll 8
        for (int f = 0; f < 64; f++) {
            // rows rg*8..+3 and rg*8+4..+7 as two broadcast LDS.128
            ulonglong2 hv0 = *reinterpret_cast<const ulonglong2*>(&cur[f * 132 + rg * 8]);
            ulonglong2 hv1 = *reinterpret_cast<const ulonglong2*>(&cur[f * 132 + rg * 8 + 4]);
            float4 w = *reinterpret_cast<const float4*>(&sW[f * 68 + cg * 4]);
            unsigned long long w0, w1, w2, w3;
            SPLAT2(w0, __float_as_uint(w.x));
            SPLAT2(w1, __float_as_uint(w.y));
            SPLAT2(w2, __float_as_uint(w.z));
            SPLAT2(w3, __float_as_uint(w.w));
            FFMA2(acc2[0][0], hv0.x, w0, acc2[0][0]);
            FFMA2(acc2[0][1], hv0.x, w1, acc2[0][1]);
            FFMA2(acc2[0][2], hv0.x, w2, acc2[0][2]);
            FFMA2(acc2[0][3], hv0.x, w3, acc2[0][3]);
            FFMA2(acc2[1][0], hv0.y, w0, acc2[1][0]);
            FFMA2(acc2[1][1], hv0.y, w1, acc2[1][1]);
            FFMA2(acc2[1][2], hv0.y, w2, acc2[1][2]);
            FFMA2(acc2[1][3], hv0.y, w3, acc2[1][3]);
            FFMA2(acc2[2][0], hv1.x, w0, acc2[2][0]);
            FFMA2(acc2[2][1], hv1.x, w1, acc2[2][1]);
            FFMA2(acc2[2][2], hv1.x, w2, acc2[2][2]);
            FFMA2(acc2[2][3], hv1.x, w3, acc2[2][3]);
            FFMA2(acc2[3][0], hv1.y, w0, acc2[3][0]);
            FFMA2(acc2[3][1], hv1.y, w1, acc2[3][1]);
            FFMA2(acc2[3][2], hv1.y, w2, acc2[3][2]);
            FFMA2(acc2[3][3], hv1.y, w3, acc2[3][3]);
        }

        // unpack: accs[j][c], j = local row 0..7 (row-pair p -> rows 2p, 2p+1)
        float accs[8][4];
#pragma unroll
        for (int p = 0; p < 4; p++)
#pragma unroll
            for (int c = 0; c < 4; c++)
                UNPACK2(accs[2 * p][c], accs[2 * p + 1][c], acc2[p][c]);

        // store Wh
#pragma unroll
        for (int j = 0; j < 8; j++) {
            int row = row0 + rg * 8 + j;
            if (row < R)
                *reinterpret_cast<float4*>(&g_Wh[(size_t)row * FD + cg * 4]) =
                    make_float4(accs[j][0], accs[j][1], accs[j][2], accs[j][3]);
        }

        // sc/sn epilogue: partial dots + 16-lane shuffle reduction over cg
        float4 av1 = *reinterpret_cast<const float4*>(&sa[cg * 4]);
        float4 av2 = *reinterpret_cast<const float4*>(&sa[64 + cg * 4]);
        float sp[8], sq[8];
#pragma unroll
        for (int j = 0; j < 8; j++) {
            sp[j] = accs[j][0] * av1.x + accs[j][1] * av1.y + accs[j][2] * av1.z + accs[j][3] * av1.w;
            sq[j] = accs[j][0] * av2.x + accs[j][1] * av2.y + accs[j][2] * av2.z + accs[j][3] * av2.w;
        }
#pragma unroll
        for (int m = 1; m < 16; m <<= 1) {
#pragma unroll
            for (int j = 0; j < 8; j++) {
                sp[j] += __shfl_xor_sync(0xffffffffu, sp[j], m);
                sq[j] += __shfl_xor_sync(0xffffffffu, sq[j], m);
            }
        }
        if (cg == 0) {
#pragma unroll
            for (int j = 0; j < 8; j++) {
                int row = row0 + rg * 8 + j;
                if (row < R) { g_sc[row] = sp[j]; g_sn[row] = sq[j]; }
            }
        }

        __syncthreads();   // all reads of cur done before next iter overwrites it
        buf ^= 1;
    }
}

// ---------------- edge+fill: x_exp, denom atomic, padded-CSR scatter --------
__global__ __launch_bounds__(256)
void edgefill_kernel(const int2* __restrict__ edge, const float* __restrict__ ew,
                     const int* __restrict__ edge_num, int N, int E) {
    int b  = blockIdx.y;
    int en = edge_num[b];
    int e0 = blockIdx.x * blockDim.x;
    if (e0 >= en) return;
    int e = e0 + threadIdx.x;
    if (e >= en) return;
    size_t idx = (size_t)b * E + e;

    int2 ed = edge[idx];
    int node = b * N + ed.x;
    int nbrg = b * N + ed.y;
    float s = g_sc[node] + g_sn[nbrg];
    float t = ew[idx] * s;
    float att1 = (t >= 0.f) ? t : LRELU_ALPHA * t;      // leaky_relu
    float x = fminf(__expf(att1), EXP_CLAMP);           // clip(exp, 0, 1e6)
    atomicAdd(&g_denom[node], x);
    int p = atomicAdd(&g_deg[node], 1);                 // cursor == degree counter
    if (p < CAP)
        g_csr[(size_t)node * CAP + p] = make_int2(nbrg, __float_as_int(x));
}

// ---------------- node pass: gather-accumulate, normalize, ReLU, store -------
__global__ __launch_bounds__(256)
void node_kernel(float* __restrict__ out, int R) {
    int g = blockIdx.x * 16 + (threadIdx.x >> 4);
    if (g >= R) return;
    int sub = threadIdx.x & 15;

    int deg = g_deg[g];
    if (deg > CAP) deg = CAP;
    const int2* row = &g_csr[(size_t)g * CAP];
    const float4* wh4 = reinterpret_cast<const float4*>(g_Wh);

    float4 acc = make_float4(0.f, 0.f, 0.f, 0.f);
    int i = 0;
    for (; i + 4 <= deg; i += 4) {
        int2 c0 = row[i + 0];
        int2 c1 = row[i + 1];
        int2 c2 = row[i + 2];
        int2 c3 = row[i + 3];
        float4 w0 = wh4[(size_t)c0.x * 16 + sub];
        float4 w1 = wh4[(size_t)c1.x * 16 + sub];
        float4 w2 = wh4[(size_t)c2.x * 16 + sub];
        float4 w3 = wh4[(size_t)c3.x * 16 + sub];
        float x0 = __int_as_float(c0.y), x1 = __int_as_float(c1.y);
        float x2 = __int_as_float(c2.y), x3 = __int_as_float(c3.y);
        acc.x += x0 * w0.x; acc.y += x0 * w0.y; acc.z += x0 * w0.z; acc.w += x0 * w0.w;
        acc.x += x1 * w1.x; acc.y += x1 * w1.y; acc.z += x1 * w1.z; acc.w += x1 * w1.w;
        acc.x += x2 * w2.x; acc.y += x2 * w2.y; acc.z += x2 * w2.z; acc.w += x2 * w2.w;
        acc.x += x3 * w3.x; acc.y += x3 * w3.y; acc.z += x3 * w3.z; acc.w += x3 * w3.w;
    }
    for (; i < deg; i++) {
        int2 c = row[i];
        float x = __int_as_float(c.y);
        float4 w = wh4[(size_t)c.x * 16 + sub];
        acc.x += x * w.x; acc.y += x * w.y; acc.z += x * w.z; acc.w += x * w.w;
    }

    float inv = 1.0f / (DENOM_EPS + g_denom[g]);
    acc.x = fmaxf(acc.x * inv, 0.f);
    acc.y = fmaxf(acc.y * inv, 0.f);
    acc.z = fmaxf(acc.z * inv, 0.f);
    acc.w = fmaxf(acc.w * inv, 0.f);
    reinterpret_cast<float4*>(out)[(size_t)g * 16 + sub] = acc;
}

// ---------------- launch ----------------
extern "C" void kernel_launch(void* const* d_in, const int* in_sizes, int n_in,
                              void* d_out, int out_size) {
    const float* h   = (const float*)d_in[0];
    const int2*  edg = (const int2*) d_in[1];
    const int*   en  = (const int*)  d_in[2];
    const float* ew  = (const float*)d_in[3];
    const float* W   = (const float*)d_in[4];
    const float* a   = (const float*)d_in[5];
    float* out = (float*)d_out;

    int B = in_sizes[2];                 // edge_num has B elements
    int E = in_sizes[3] / B;             // edge_weight is B*E
    int N = in_sizes[0] / (B * FD);      // h is B*N*F
    int R = B * N;
    int NT = (R + TROWS - 1) / TROWS;

    cudaFuncSetAttribute(gemm_kernel,
                         cudaFuncAttributeMaxDynamicSharedMemorySize,
                         GEMM_SMEM_BYTES);

    gemm_kernel<<<GEMM_GRID, 256, GEMM_SMEM_BYTES>>>(h, W, a, R, NT);

    dim3 ge((E + 255) / 256, B);
    edgefill_kernel<<<ge, 256>>>(edg, ew, en, N, E);

    node_kernel<<<(R + 15) / 16, 256>>>(out, R);
}

// round 11
// speedup vs baseline: 3.6028x; 1.0072x over previous
#include <cuda_runtime.h>
#include <cstdint>

// Problem constants (GraphAttentionLayer: B=4, N=16384, E=262144, F=64)
#define FD   64
#define MAXB 4
#define MAXN 16384
#define MAXE 262144
#define MAXR (MAXB * MAXN)
#define CAP  128            // padded-CSR capacity per node (deg ~ Poisson(<=16))

#define LRELU_ALPHA 0.01f
#define EXP_CLAMP   1000000.0f
#define DENOM_EPS   1e-10f

// ---------------- device scratch (no allocations allowed) ----------------
__device__ float g_Wh[(size_t)MAXR * FD];          // 16 MB
__device__ float g_sc[MAXR];                       // Wh . a[0:64]
__device__ float g_sn[MAXR];                       // Wh . a[64:128]
__device__ float g_denom[MAXR];                    // segment sums of x_exp
__device__ int   g_deg[MAXR];                      // per-node cursor/degree
__device__ int2  g_csr[(size_t)MAXR * CAP];        // padded: (nbr_global, bits(x_exp))

// ---------------- packed fp32x2 helpers (sm_103a FFMA2 path) ----------------
#define FFMA2(d, a, b, c) \
    asm("fma.rn.f32x2 %0, %1, %2, %3;" : "=l"(d) : "l"(a), "l"(b), "l"(c))
#define SPLAT2(d, x) \
    asm("mov.b64 %0, {%1, %2};" : "=l"(d) : "r"(x), "r"(x))
#define UNPACK2(lo, hi, v) \
    asm("mov.b64 {%0, %1}, %2;" : "=f"(lo), "=f"(hi) : "l"(v))

__device__ __forceinline__ uint32_t smem_u32(const void* p) {
    return (uint32_t)__cvta_generic_to_shared(p);
}

// ---------------- GEMM: 1 tile (64 rows) per block, high occupancy, FFMA2 ---
// 256 threads = 16 row-groups (4 rows) x 16 col-groups (4 cols).
// smem ~36 KB static -> 5-6 blocks/SM; inter-block overlap hides prologue.
__global__ __launch_bounds__(256)
void gemm_kernel(const float* __restrict__ h, const float* __restrict__ W,
                 const float* __restrict__ a, int R) {
    __shared__ float sW[64 * 68];    // W transposed: sW[f*68+o]
    __shared__ float sh[64 * 72];    // h transposed: sh[f*72+r]
    __shared__ float sa[128];

    int tid = threadIdx.x;
    int row0 = blockIdx.x * 64;

    // fused init: zero denom/deg for this tile's rows
    if (tid < 64) {
        int row = row0 + tid;
        if (row < R) { g_denom[row] = 0.f; g_deg[row] = 0; }
    }

    // stage h tile transposed via cp.async (gmem coalesced, smem scattered)
#pragma unroll
    for (int k = 0; k < 16; k++) {
        int i = tid + k * 256;
        int f = i & 63, r = i >> 6;
        int row = row0 + r;
        if (row < R)
            asm volatile("cp.async.ca.shared.global [%0], [%1], 4;"
                         :: "r"(smem_u32(sh + f * 72 + r)),
                            "l"(h + (size_t)row * FD + f) : "memory");
    }
    // stage W transposed via cp.async (same pattern: W[o][f] -> sW[f*68+o])
#pragma unroll
    for (int k = 0; k < 16; k++) {
        int i = tid + k * 256;
        int f = i & 63, o = i >> 6;
        asm volatile("cp.async.ca.shared.global [%0], [%1], 4;"
                     :: "r"(smem_u32(sW + f * 68 + o)),
                        "l"(W + (size_t)o * FD + f) : "memory");
    }
    asm volatile("cp.async.commit_group;" ::: "memory");
    if (tid < 128) sa[tid] = a[tid];
    asm volatile("cp.async.wait_group 0;" ::: "memory");
    __syncthreads();

    int rg = tid >> 4;      // rows rg*4 .. rg*4+3
    int cg = tid & 15;      // cols cg*4 .. cg*4+3

    // mainloop: 2 LDS.128 + 4 splats + 8 FFMA2 per f
    unsigned long long acc2[2][4];   // [row-pair][col]
#pragma unroll
    for (int p = 0; p < 2; p++)
#pragma unroll
        for (int c = 0; c < 4; c++) acc2[p][c] = 0ull;

#pragma unroll 8
    for (int f = 0; f < 64; f++) {
        ulonglong2 hv = *reinterpret_cast<const ulonglong2*>(&sh[f * 72 + rg * 4]);
        float4 w = *reinterpret_cast<const float4*>(&sW[f * 68 + cg * 4]);
        unsigned long long w0, w1, w2, w3;
        SPLAT2(w0, __float_as_uint(w.x));
        SPLAT2(w1, __float_as_uint(w.y));
        SPLAT2(w2, __float_as_uint(w.z));
        SPLAT2(w3, __float_as_uint(w.w));
        FFMA2(acc2[0][0], hv.x, w0, acc2[0][0]);
        FFMA2(acc2[0][1], hv.x, w1, acc2[0][1]);
        FFMA2(acc2[0][2], hv.x, w2, acc2[0][2]);
        FFMA2(acc2[0][3], hv.x, w3, acc2[0][3]);
        FFMA2(acc2[1][0], hv.y, w0, acc2[1][0]);
        FFMA2(acc2[1][1], hv.y, w1, acc2[1][1]);
        FFMA2(acc2[1][2], hv.y, w2, acc2[1][2]);
        FFMA2(acc2[1][3], hv.y, w3, acc2[1][3]);
    }

    // unpack: accs[j][c], rows j = 2p + half
    float accs[4][4];
#pragma unroll
    for (int p = 0; p < 2; p++)
#pragma unroll
        for (int c = 0; c < 4; c++)
            UNPACK2(accs[2 * p][c], accs[2 * p + 1][c], acc2[p][c]);

    // store Wh
#pragma unroll
    for (int j = 0; j < 4; j++) {
        int row = row0 + rg * 4 + j;
        if (row < R)
            *reinterpret_cast<float4*>(&g_Wh[(size_t)row * FD + cg * 4]) =
                make_float4(accs[j][0], accs[j][1], accs[j][2], accs[j][3]);
    }

    // sc/sn epilogue: partial dots + 16-lane shuffle reduction over cg
    float4 av1 = *reinterpret_cast<const float4*>(&sa[cg * 4]);
    float4 av2 = *reinterpret_cast<const float4*>(&sa[64 + cg * 4]);
    float sp[4], sq[4];
#pragma unroll
    for (int j = 0; j < 4; j++) {
        sp[j] = accs[j][0] * av1.x + accs[j][1] * av1.y + accs[j][2] * av1.z + accs[j][3] * av1.w;
        sq[j] = accs[j][0] * av2.x + accs[j][1] * av2.y + accs[j][2] * av2.z + accs[j][3] * av2.w;
    }
#pragma unroll
    for (int m = 1; m < 16; m <<= 1) {
#pragma unroll
        for (int j = 0; j < 4; j++) {
            sp[j] += __shfl_xor_sync(0xffffffffu, sp[j], m);
            sq[j] += __shfl_xor_sync(0xffffffffu, sq[j], m);
        }
    }
    if (cg == 0) {
#pragma unroll
        for (int j = 0; j < 4; j++) {
            int row = row0 + rg * 4 + j;
            if (row < R) { g_sc[row] = sp[j]; g_sn[row] = sq[j]; }
        }
    }
}

// ---------------- edge+fill: x_exp, denom atomic, padded-CSR scatter --------
__global__ __launch_bounds__(256)
void edgefill_kernel(const int2* __restrict__ edge, const float* __restrict__ ew,
                     const int* __restrict__ edge_num, int N, int E) {
    int b  = blockIdx.y;
    int en = edge_num[b];
    int e0 = blockIdx.x * blockDim.x;
    if (e0 >= en) return;
    int e = e0 + threadIdx.x;
    if (e >= en) return;
    size_t idx = (size_t)b * E + e;

    int2 ed = edge[idx];
    int node = b * N + ed.x;
    int nbrg = b * N + ed.y;
    float s = g_sc[node] + g_sn[nbrg];
    float t = ew[idx] * s;
    float att1 = (t >= 0.f) ? t : LRELU_ALPHA * t;      // leaky_relu
    float x = fminf(__expf(att1), EXP_CLAMP);           // clip(exp, 0, 1e6)
    atomicAdd(&g_denom[node], x);
    int p = atomicAdd(&g_deg[node], 1);                 // cursor == degree counter
    if (p < CAP)
        g_csr[(size_t)node * CAP + p] = make_int2(nbrg, __float_as_int(x));
}

// ---------------- node pass: gather-accumulate, normalize, ReLU, store -------
__global__ __launch_bounds__(256)
void node_kernel(float* __restrict__ out, int R) {
    int g = blockIdx.x * 16 + (threadIdx.x >> 4);
    if (g >= R) return;
    int sub = threadIdx.x & 15;

    int deg = g_deg[g];
    if (deg > CAP) deg = CAP;
    const int2* row = &g_csr[(size_t)g * CAP];
    const float4* wh4 = reinterpret_cast<const float4*>(g_Wh);

    float4 acc = make_float4(0.f, 0.f, 0.f, 0.f);
    int i = 0;
    for (; i + 4 <= deg; i += 4) {
        int2 c0 = row[i + 0];
        int2 c1 = row[i + 1];
        int2 c2 = row[i + 2];
        int2 c3 = row[i + 3];
        float4 w0 = wh4[(size_t)c0.x * 16 + sub];
        float4 w1 = wh4[(size_t)c1.x * 16 + sub];
        float4 w2 = wh4[(size_t)c2.x * 16 + sub];
        float4 w3 = wh4[(size_t)c3.x * 16 + sub];
        float x0 = __int_as_float(c0.y), x1 = __int_as_float(c1.y);
        float x2 = __int_as_float(c2.y), x3 = __int_as_float(c3.y);
        acc.x += x0 * w0.x; acc.y += x0 * w0.y; acc.z += x0 * w0.z; acc.w += x0 * w0.w;
        acc.x += x1 * w1.x; acc.y += x1 * w1.y; acc.z += x1 * w1.z; acc.w += x1 * w1.w;
        acc.x += x2 * w2.x; acc.y += x2 * w2.y; acc.z += x2 * w2.z; acc.w += x2 * w2.w;
        acc.x += x3 * w3.x; acc.y += x3 * w3.y; acc.z += x3 * w3.z; acc.w += x3 * w3.w;
    }
    for (; i < deg; i++) {
        int2 c = row[i];
        float x = __int_as_float(c.y);
        float4 w = wh4[(size_t)c.x * 16 + sub];
        acc.x += x * w.x; acc.y += x * w.y; acc.z += x * w.z; acc.w += x * w.w;
    }

    float inv = 1.0f / (DENOM_EPS + g_denom[g]);
    acc.x = fmaxf(acc.x * inv, 0.f);
    acc.y = fmaxf(acc.y * inv, 0.f);
    acc.z = fmaxf(acc.z * inv, 0.f);
    acc.w = fmaxf(acc.w * inv, 0.f);
    reinterpret_cast<float4*>(out)[(size_t)g * 16 + sub] = acc;
}

// ---------------- launch ----------------
extern "C" void kernel_launch(void* const* d_in, const int* in_sizes, int n_in,
                              void* d_out, int out_size) {
    const float* h   = (const float*)d_in[0];
    const int2*  edg = (const int2*) d_in[1];
    const int*   en  = (const int*)  d_in[2];
    const float* ew  = (const float*)d_in[3];
    const float* W   = (const float*)d_in[4];
    const float* a   = (const float*)d_in[5];
    float* out = (float*)d_out;

    int B = in_sizes[2];                 // edge_num has B elements
    int E = in_sizes[3] / B;             // edge_weight is B*E
    int N = in_sizes[0] / (B * FD);      // h is B*N*F
    int R = B * N;

    gemm_kernel<<<(R + 63) / 64, 256>>>(h, W, a, R);

    dim3 ge((E + 255) / 256, B);
    edgefill_kernel<<<ge, 256>>>(edg, ew, en, N, E);

    node_kernel<<<(R + 15) / 16, 256>>>(out, R);
}

// round 14
// speedup vs baseline: 3.7103x; 1.0298x over previous
#include <cuda_runtime.h>
#include <cstdint>

// Problem constants (GraphAttentionLayer: B=4, N=16384, E=262144, F=64)
#define FD   64
#define MAXB 4
#define MAXN 16384
#define MAXE 262144
#define MAXR (MAXB * MAXN)
#define CAP  128            // padded-CSR capacity per node (deg ~ Poisson(<=16))

#define LRELU_ALPHA 0.01f
#define EXP_CLAMP   1000000.0f
#define DENOM_EPS   1e-10f

// ---------------- device scratch (no allocations allowed) ----------------
__device__ float g_Wh[(size_t)MAXR * FD];          // 16 MB
__device__ float g_sc[MAXR];                       // Wh . a[0:64]
__device__ float g_sn[MAXR];                       // Wh . a[64:128]
__device__ float g_denom[MAXR];                    // segment sums of x_exp
__device__ int   g_deg[MAXR];                      // per-node cursor/degree
__device__ int2  g_csr[(size_t)MAXR * CAP];        // padded: (nbr_global, bits(x_exp))

// ---------------- packed fp32x2 helpers (sm_103a FFMA2 path) ----------------
#define FFMA2(d, a, b, c) \
    asm("fma.rn.f32x2 %0, %1, %2, %3;" : "=l"(d) : "l"(a), "l"(b), "l"(c))
#define SPLAT2(d, x) \
    asm("mov.b64 %0, {%1, %2};" : "=l"(d) : "r"(x), "r"(x))
#define UNPACK2(lo, hi, v) \
    asm("mov.b64 {%0, %1}, %2;" : "=f"(lo), "=f"(hi) : "l"(v))

__device__ __forceinline__ uint32_t smem_u32(const void* p) {
    return (uint32_t)__cvta_generic_to_shared(p);
}

// ---------------- GEMM: 1 tile (64 rows)/block, conflict-free staging -------
// 256 threads = 16 row-groups (4 rows) x 16 col-groups (4 cols).
// Staging remap: warp covers 8 f x 4 r -> smem banks 4*(f%8)+r all distinct.
__global__ __launch_bounds__(256)
void gemm_kernel(const float* __restrict__ h, const float* __restrict__ W,
                 const float* __restrict__ a, int R) {
    __shared__ float sW[64 * 68];    // W transposed: sW[f*68+o]
    __shared__ float sh[64 * 68];    // h transposed: sh[f*68+r]
    __shared__ float sa[128];

    int tid = threadIdx.x;
    int row0 = blockIdx.x * 64;

    // fused init: zero denom/deg for this tile's rows
    if (tid < 64) {
        int row = row0 + tid;
        if (row < R) { g_denom[row] = 0.f; g_deg[row] = 0; }
    }

    // stage h tile transposed, conflict-free: f=(i>>2)&63, r=(i&3)|((i>>8)<<2)
#pragma unroll
    for (int k = 0; k < 16; k++) {
        int i = tid + k * 256;
        int f = (i >> 2) & 63;
        int r = (i & 3) | ((i >> 8) << 2);
        int row = row0 + r;
        if (row < R)
            asm volatile("cp.async.ca.shared.global [%0], [%1], 4;"
                         :: "r"(smem_u32(sh + f * 68 + r)),
                            "l"(h + (size_t)row * FD + f) : "memory");
    }
    // stage W transposed, same conflict-free mapping: W[o][f] -> sW[f*68+o]
#pragma unroll
    for (int k = 0; k < 16; k++) {
        int i = tid + k * 256;
        int f = (i >> 2) & 63;
        int o = (i & 3) | ((i >> 8) << 2);
        asm volatile("cp.async.ca.shared.global [%0], [%1], 4;"
                     :: "r"(smem_u32(sW + f * 68 + o)),
                        "l"(W + (size_t)o * FD + f) : "memory");
    }
    asm volatile("cp.async.commit_group;" ::: "memory");
    if (tid < 128) sa[tid] = a[tid];
    asm volatile("cp.async.wait_group 0;" ::: "memory");
    __syncthreads();

    int rg = tid >> 4;      // rows rg*4 .. rg*4+3
    int cg = tid & 15;      // cols cg*4 .. cg*4+3

    // mainloop: 2 LDS.128 + 4 splats + 8 FFMA2 per f
    unsigned long long acc2[2][4];   // [row-pair][col]
#pragma unroll
    for (int p = 0; p < 2; p++)
#pragma unroll
        for (int c = 0; c < 4; c++) acc2[p][c] = 0ull;

#pragma unroll 8
    for (int f = 0; f < 64; f++) {
        ulonglong2 hv = *reinterpret_cast<const ulonglong2*>(&sh[f * 68 + rg * 4]);
        float4 w = *reinterpret_cast<const float4*>(&sW[f * 68 + cg * 4]);
        unsigned long long w0, w1, w2, w3;
        SPLAT2(w0, __float_as_uint(w.x));
        SPLAT2(w1, __float_as_uint(w.y));
        SPLAT2(w2, __float_as_uint(w.z));
        SPLAT2(w3, __float_as_uint(w.w));
        FFMA2(acc2[0][0], hv.x, w0, acc2[0][0]);
        FFMA2(acc2[0][1], hv.x, w1, acc2[0][1]);
        FFMA2(acc2[0][2], hv.x, w2, acc2[0][2]);
        FFMA2(acc2[0][3], hv.x, w3, acc2[0][3]);
        FFMA2(acc2[1][0], hv.y, w0, acc2[1][0]);
        FFMA2(acc2[1][1], hv.y, w1, acc2[1][1]);
        FFMA2(acc2[1][2], hv.y, w2, acc2[1][2]);
        FFMA2(acc2[1][3], hv.y, w3, acc2[1][3]);
    }

    // unpack: accs[j][c], rows j = 2p + half
    float accs[4][4];
#pragma unroll
    for (int p = 0; p < 2; p++)
#pragma unroll
        for (int c = 0; c < 4; c++)
            UNPACK2(accs[2 * p][c], accs[2 * p + 1][c], acc2[p][c]);

    // store Wh
#pragma unroll
    for (int j = 0; j < 4; j++) {
        int row = row0 + rg * 4 + j;
        if (row < R)
            *reinterpret_cast<float4*>(&g_Wh[(size_t)row * FD + cg * 4]) =
                make_float4(accs[j][0], accs[j][1], accs[j][2], accs[j][3]);
    }

    // sc/sn epilogue: partial dots + 16-lane shuffle reduction over cg
    float4 av1 = *reinterpret_cast<const float4*>(&sa[cg * 4]);
    float4 av2 = *reinterpret_cast<const float4*>(&sa[64 + cg * 4]);
    float sp[4], sq[4];
#pragma unroll
    for (int j = 0; j < 4; j++) {
        sp[j] = accs[j][0] * av1.x + accs[j][1] * av1.y + accs[j][2] * av1.z + accs[j][3] * av1.w;
        sq[j] = accs[j][0] * av2.x + accs[j][1] * av2.y + accs[j][2] * av2.z + accs[j][3] * av2.w;
    }
#pragma unroll
    for (int m = 1; m < 16; m <<= 1) {
#pragma unroll
        for (int j = 0; j < 4; j++) {
            sp[j] += __shfl_xor_sync(0xffffffffu, sp[j], m);
            sq[j] += __shfl_xor_sync(0xffffffffu, sq[j], m);
        }
    }
    if (cg == 0) {
#pragma unroll
        for (int j = 0; j < 4; j++) {
            int row = row0 + rg * 4 + j;
            if (row < R) { g_sc[row] = sp[j]; g_sn[row] = sq[j]; }
        }
    }
}

// ---------------- edge+fill: x_exp, denom atomic, padded-CSR scatter --------
__global__ __launch_bounds__(256)
void edgefill_kernel(const int2* __restrict__ edge, const float* __restrict__ ew,
                     const int* __restrict__ edge_num, int N, int E) {
    int b  = blockIdx.y;
    int en = edge_num[b];
    int e0 = blockIdx.x * blockDim.x;
    if (e0 >= en) return;
    int e = e0 + threadIdx.x;
    if (e >= en) return;
    size_t idx = (size_t)b * E + e;

    int2 ed = edge[idx];
    int node = b * N + ed.x;
    int nbrg = b * N + ed.y;
    float s = g_sc[node] + g_sn[nbrg];
    float t = ew[idx] * s;
    float att1 = (t >= 0.f) ? t : LRELU_ALPHA * t;      // leaky_relu
    float x = fminf(__expf(att1), EXP_CLAMP);           // clip(exp, 0, 1e6)
    atomicAdd(&g_denom[node], x);
    int p = atomicAdd(&g_deg[node], 1);                 // cursor == degree counter
    if (p < CAP)
        g_csr[(size_t)node * CAP + p] = make_int2(nbrg, __float_as_int(x));
}

// ---------------- node pass: gather-accumulate, normalize, ReLU, store -------
__global__ __launch_bounds__(256)
void node_kernel(float* __restrict__ out, int R) {
    int g = blockIdx.x * 16 + (threadIdx.x >> 4);
    if (g >= R) return;
    int sub = threadIdx.x & 15;

    int deg = g_deg[g];
    if (deg > CAP) deg = CAP;
    const int2* row = &g_csr[(size_t)g * CAP];
    const float4* wh4 = reinterpret_cast<const float4*>(g_Wh);

    float4 acc = make_float4(0.f, 0.f, 0.f, 0.f);
    int i = 0;
    for (; i + 4 <= deg; i += 4) {
        int2 c0 = row[i + 0];
        int2 c1 = row[i + 1];
        int2 c2 = row[i + 2];
        int2 c3 = row[i + 3];
        float4 w0 = wh4[(size_t)c0.x * 16 + sub];
        float4 w1 = wh4[(size_t)c1.x * 16 + sub];
        float4 w2 = wh4[(size_t)c2.x * 16 + sub];
        float4 w3 = wh4[(size_t)c3.x * 16 + sub];
        float x0 = __int_as_float(c0.y), x1 = __int_as_float(c1.y);
        float x2 = __int_as_float(c2.y), x3 = __int_as_float(c3.y);
        acc.x += x0 * w0.x; acc.y += x0 * w0.y; acc.z += x0 * w0.z; acc.w += x0 * w0.w;
        acc.x += x1 * w1.x; acc.y += x1 * w1.y; acc.z += x1 * w1.z; acc.w += x1 * w1.w;
        acc.x += x2 * w2.x; acc.y += x2 * w2.y; acc.z += x2 * w2.z; acc.w += x2 * w2.w;
        acc.x += x3 * w3.x; acc.y += x3 * w3.y; acc.z += x3 * w3.z; acc.w += x3 * w3.w;
    }
    for (; i < deg; i++) {
        int2 c = row[i];
        float x = __int_as_float(c.y);
        float4 w = wh4[(size_t)c.x * 16 + sub];
        acc.x += x * w.x; acc.y += x * w.y; acc.z += x * w.z; acc.w += x * w.w;
    }

    float inv = 1.0f / (DENOM_EPS + g_denom[g]);
    acc.x = fmaxf(acc.x * inv, 0.f);
    acc.y = fmaxf(acc.y * inv, 0.f);
    acc.z = fmaxf(acc.z * inv, 0.f);
    acc.w = fmaxf(acc.w * inv, 0.f);
    reinterpret_cast<float4*>(out)[(size_t)g * 16 + sub] = acc;
}

// ---------------- launch ----------------
extern "C" void kernel_launch(void* const* d_in, const int* in_sizes, int n_in,
                              void* d_out, int out_size) {
    const float* h   = (const float*)d_in[0];
    const int2*  edg = (const int2*) d_in[1];
    const int*   en  = (const int*)  d_in[2];
    const float* ew  = (const float*)d_in[3];
    const float* W   = (const float*)d_in[4];
    const float* a   = (const float*)d_in[5];
    float* out = (float*)d_out;

    int B = in_sizes[2];                 // edge_num has B elements
    int E = in_sizes[3] / B;             // edge_weight is B*E
    int N = in_sizes[0] / (B * FD);      // h is B*N*F
    int R = B * N;

    gemm_kernel<<<(R + 63) / 64, 256>>>(h, W, a, R);

    dim3 ge((E + 255) / 256, B);
    edgefill_kernel<<<ge, 256>>>(edg, ew, en, N, E);

    node_kernel<<<(R + 15) / 16, 256>>>(out, R);
}